// round 7
// baseline (speedup 1.0000x reference)
#include <cuda_runtime.h>
#include <cuda_bf16.h>
#include <cstdint>
#include <math.h>

// Problem dims (fixed by the dataset)
#define BB 16
#define SS 1024
#define HH 512
#define CC 7
#define MM (BB * SS)        // 16384 rows
#define H3 (3 * HH)         // 1536
#define EPSV 1e-10f

// GEMM tiling
#define BM 128
#define BN 128
#define BK 32
#define LDA 40              // halves, padded (80B rows: cp.async-aligned, ldmatrix conflict-free)
#define LDB 136             // halves, padded (272B rows)
#define NSTG 3
#define STAGE_H (2 * BM * LDA + 2 * BK * LDB)      // halves per stage = 18944
#define SMEM_BYTES (NSTG * STAGE_H * 2)            // 113664 B

// ----------------------------------------------------------------------------
// Static scratch (bf16 hi/lo planes; no allocations anywhere)
// ----------------------------------------------------------------------------
__device__ __nv_bfloat16 g_fh[3 * MM * HH],  g_fl[3 * MM * HH];    // text/audio/visual
__device__ __nv_bfloat16 g_toth[MM * HH],    g_totl[MM * HH];
__device__ __nv_bfloat16 g_Gh[3 * MM * HH],  g_Gl[3 * MM * HH];
__device__ __nv_bfloat16 g_Th[MM * HH],      g_Tl[MM * HH];
__device__ __nv_bfloat16 g_h0h[MM * H3],     g_h0l[MM * H3];
__device__ __nv_bfloat16 g_adjh[BB * SS * SS], g_adjl[BB * SS * SS];
__device__ __nv_bfloat16 g_tmph[MM * HH],    g_tmpl[MM * HH];
__device__ __nv_bfloat16 g_hh[MM * HH],      g_hl[MM * HH];
__device__ __nv_bfloat16 g_Awh[HH * HH], g_Awl[HH * HH];
__device__ __nv_bfloat16 g_Whh[HH * HH], g_Whl[HH * HH];
__device__ __nv_bfloat16 g_W0h[H3 * HH], g_W0l[H3 * HH];
__device__ __nv_bfloat16 g_W1h[HH * HH], g_W1l[HH * HH];
__device__ __nv_bfloat16 g_W2h[HH * HH], g_W2l[HH * HH];
__device__ float g_ent[3 * MM];
__device__ float g_dsi[BB * SS];
__device__ float g_wlast[HH];
__device__ float g_WcT[CC * HH];

// ----------------------------------------------------------------------------
// Helpers
// ----------------------------------------------------------------------------
__device__ __forceinline__ unsigned s2u(const void* p) {
    return (unsigned)__cvta_generic_to_shared(p);
}

__device__ __forceinline__ void split4_store(float4 v, __nv_bfloat16* h,
                                             __nv_bfloat16* l, long long idx) {
    __nv_bfloat16 hx = __float2bfloat16(v.x);
    __nv_bfloat16 hy = __float2bfloat16(v.y);
    __nv_bfloat16 hz = __float2bfloat16(v.z);
    __nv_bfloat16 hw = __float2bfloat16(v.w);
    __nv_bfloat16 lx = __float2bfloat16(v.x - __bfloat162float(hx));
    __nv_bfloat16 ly = __float2bfloat16(v.y - __bfloat162float(hy));
    __nv_bfloat16 lz = __float2bfloat16(v.z - __bfloat162float(hz));
    __nv_bfloat16 lw = __float2bfloat16(v.w - __bfloat162float(hw));
    __nv_bfloat162* ph = (__nv_bfloat162*)(h + idx);
    __nv_bfloat162* pl = (__nv_bfloat162*)(l + idx);
    ph[0] = __nv_bfloat162(hx, hy); ph[1] = __nv_bfloat162(hz, hw);
    pl[0] = __nv_bfloat162(lx, ly); pl[1] = __nv_bfloat162(lz, lw);
}

#define MMA16816(d, a, b)                                                  \
    asm volatile(                                                          \
        "mma.sync.aligned.m16n8k16.row.col.f32.bf16.bf16.f32 "             \
        "{%0,%1,%2,%3}, {%4,%5,%6,%7}, {%8,%9}, {%0,%1,%2,%3};\n"          \
        : "+f"(d[0]), "+f"(d[1]), "+f"(d[2]), "+f"(d[3])                   \
        : "r"(a[0]), "r"(a[1]), "r"(a[2]), "r"(a[3]), "r"(b[0]), "r"(b[1]))

#define LDSM_X4(r0, r1, r2, r3, addr)                                      \
    asm volatile("ldmatrix.sync.aligned.m8n8.x4.shared.b16 "               \
                 "{%0,%1,%2,%3}, [%4];\n"                                  \
                 : "=r"(r0), "=r"(r1), "=r"(r2), "=r"(r3) : "r"(addr))

#define LDSM_X4T(r0, r1, r2, r3, addr)                                     \
    asm volatile("ldmatrix.sync.aligned.m8n8.x4.trans.shared.b16 "         \
                 "{%0,%1,%2,%3}, [%4];\n"                                  \
                 : "=r"(r0), "=r"(r1), "=r"(r2), "=r"(r3) : "r"(addr))

#define CP16(dst, src)                                                     \
    asm volatile("cp.async.cg.shared.global [%0], [%1], 16;\n"             \
                 :: "r"(dst), "l"(src))
#define CP_COMMIT asm volatile("cp.async.commit_group;\n" ::: "memory")
#define CP_WAIT(n) asm volatile("cp.async.wait_group %0;\n" :: "n"(n) : "memory")

// ----------------------------------------------------------------------------
// bf16-split tensor-core GEMM, 3-stage cp.async pipeline, 1 barrier per K-step.
// C = A @ B (+bias+relu). All operands bf16 hi/lo planes. 3 MMAs per logical.
// ----------------------------------------------------------------------------
template <int EPI>   // 0 = none, 1 = bias+relu
__global__ void __launch_bounds__(256) mma_gemm(
    const __nv_bfloat16* __restrict__ Ahg, const __nv_bfloat16* __restrict__ Alg,
    const __nv_bfloat16* __restrict__ Bhg, const __nv_bfloat16* __restrict__ Blg,
    const float* __restrict__ bias,
    __nv_bfloat16* __restrict__ Chg, __nv_bfloat16* __restrict__ Clg,
    int M, int N, int K, long long sA, long long sB, long long sC)
{
    extern __shared__ __nv_bfloat16 sm[];
    // stage layout (halves): Ah[0,5120) Al[5120,10240) Bh[10240,14592) Bl[14592,18944)

    const __nv_bfloat16* Ah = Ahg + (long long)blockIdx.z * sA;
    const __nv_bfloat16* Al = Alg + (long long)blockIdx.z * sA;
    const __nv_bfloat16* Bh = Bhg + (long long)blockIdx.z * sB;
    const __nv_bfloat16* Bl = Blg + (long long)blockIdx.z * sB;
    __nv_bfloat16* Ch = Chg + (long long)blockIdx.z * sC;
    __nv_bfloat16* Cl = Clg + (long long)blockIdx.z * sC;

    int t = threadIdx.x, lane = t & 31, wid = t >> 5;
    int warp_m = wid >> 2, warp_n = wid & 3;    // 2 x 4 warps
    int brow = blockIdx.y * BM, bcol = blockIdx.x * BN;
    int KT = K / BK;

    float acc[4][4][4];
    #pragma unroll
    for (int i = 0; i < 4; i++)
        #pragma unroll
        for (int j = 0; j < 4; j++)
            #pragma unroll
            for (int q = 0; q < 4; q++) acc[i][j][q] = 0.0f;

    // tile loader: 8x cp.async 16B per thread into stage s
    auto load_tile = [&](int kt, int s) {
        int k0 = kt * BK;
        __nv_bfloat16* st = sm + s * STAGE_H;
        #pragma unroll
        for (int i = 0; i < 2; i++) {
            int q = t + i * 256;
            int ra = q >> 2, ca = (q & 3) << 3;         // A: 128 rows x 4 chunks
            long long asrc = (long long)(brow + ra) * K + k0 + ca;
            CP16(s2u(st + ra * LDA + ca), Ah + asrc);
            CP16(s2u(st + BM * LDA + ra * LDA + ca), Al + asrc);
            int rb = q >> 4, cb = (q & 15) << 3;        // B: 32 rows x 16 chunks
            long long bsrc = (long long)(k0 + rb) * N + bcol + cb;
            CP16(s2u(st + 2 * BM * LDA + rb * LDB + cb), Bh + bsrc);
            CP16(s2u(st + 2 * BM * LDA + BK * LDB + rb * LDB + cb), Bl + bsrc);
        }
    };

    load_tile(0, 0); CP_COMMIT;
    load_tile(1, 1); CP_COMMIT;

    int s = 0;
    for (int kt = 0; kt < KT; kt++) {
        // stage kt ready; on the last 2 iters no more commits follow, so drain fully
        if (kt + 2 < KT) { CP_WAIT(1); } else { CP_WAIT(0); }
        __syncthreads();   // data visible to all + all warps done with stage (kt-1)%3

        if (kt + 2 < KT) { load_tile(kt + 2, (s + 2) % NSTG); CP_COMMIT; }

        const __nv_bfloat16* cAh = sm + s * STAGE_H;
        const __nv_bfloat16* cAl = cAh + BM * LDA;
        const __nv_bfloat16* cBh = cAh + 2 * BM * LDA;
        const __nv_bfloat16* cBl = cBh + BK * LDB;

        #pragma unroll
        for (int kk = 0; kk < BK; kk += 16) {
            unsigned ah[4][4], al[4][4], bh[4][2], bl[4][2];
            int arow = warp_m * 64 + (lane & 15);
            int acol = kk + ((lane >> 4) << 3);
            #pragma unroll
            for (int tm = 0; tm < 4; tm++) {
                LDSM_X4(ah[tm][0], ah[tm][1], ah[tm][2], ah[tm][3],
                        s2u(&cAh[(arow + tm * 16) * LDA + acol]));
                LDSM_X4(al[tm][0], al[tm][1], al[tm][2], al[tm][3],
                        s2u(&cAl[(arow + tm * 16) * LDA + acol]));
            }
            int brow_ = kk + (lane & 15);
            #pragma unroll
            for (int tp = 0; tp < 2; tp++) {
                int bc = warp_n * 32 + tp * 16 + ((lane >> 4) << 3);
                LDSM_X4T(bh[2 * tp][0], bh[2 * tp][1],
                         bh[2 * tp + 1][0], bh[2 * tp + 1][1],
                         s2u(&cBh[brow_ * LDB + bc]));
                LDSM_X4T(bl[2 * tp][0], bl[2 * tp][1],
                         bl[2 * tp + 1][0], bl[2 * tp + 1][1],
                         s2u(&cBl[brow_ * LDB + bc]));
            }
            #pragma unroll
            for (int tm = 0; tm < 4; tm++)
                #pragma unroll
                for (int tn = 0; tn < 4; tn++) {
                    MMA16816(acc[tm][tn], ah[tm], bh[tn]);
                    MMA16816(acc[tm][tn], ah[tm], bl[tn]);
                    MMA16816(acc[tm][tn], al[tm], bh[tn]);
                }
        }
        s = (s + 1) % NSTG;
    }

    // ---- epilogue: (bias+relu) then split to hi/lo planes ----
    int g = lane >> 2, tig = lane & 3;
    #pragma unroll
    for (int tm = 0; tm < 4; tm++)
        #pragma unroll
        for (int tn = 0; tn < 4; tn++) {
            int row = brow + warp_m * 64 + tm * 16 + g;
            int col = bcol + warp_n * 32 + tn * 8 + tig * 2;
            float2 v0 = make_float2(acc[tm][tn][0], acc[tm][tn][1]);
            float2 v1 = make_float2(acc[tm][tn][2], acc[tm][tn][3]);
            if (EPI == 1) {
                float b0 = bias[col], b1 = bias[col + 1];
                v0.x = fmaxf(v0.x + b0, 0.0f); v0.y = fmaxf(v0.y + b1, 0.0f);
                v1.x = fmaxf(v1.x + b0, 0.0f); v1.y = fmaxf(v1.y + b1, 0.0f);
            }
            #pragma unroll
            for (int rr = 0; rr < 2; rr++) {
                float2 v = rr ? v1 : v0;
                long long idx = (long long)(row + rr * 8) * N + col;
                __nv_bfloat16 h0 = __float2bfloat16(v.x);
                __nv_bfloat16 h1 = __float2bfloat16(v.y);
                __nv_bfloat16 l0 = __float2bfloat16(v.x - __bfloat162float(h0));
                __nv_bfloat16 l1 = __float2bfloat16(v.y - __bfloat162float(h1));
                *(__nv_bfloat162*)(Ch + idx) = __nv_bfloat162(h0, h1);
                *(__nv_bfloat162*)(Cl + idx) = __nv_bfloat162(l0, l1);
            }
        }
}

// ----------------------------------------------------------------------------
// Fused: entropy + bf16 split of feats + total
// ----------------------------------------------------------------------------
__global__ void prep_feats(const float* __restrict__ text,
                           const float* __restrict__ audio,
                           const float* __restrict__ visual) {
    __shared__ float sh[3][4];
    long long r = blockIdx.x;
    int tid = threadIdx.x, lane = tid & 31, w = tid >> 5;
    long long off = r * HH + tid * 4;
    float4 v0 = *(const float4*)(text + off);
    float4 v1 = *(const float4*)(audio + off);
    float4 v2 = *(const float4*)(visual + off);

    float a0x = fabsf(v0.x), a0y = fabsf(v0.y), a0z = fabsf(v0.z), a0w = fabsf(v0.w);
    float a1x = fabsf(v1.x), a1y = fabsf(v1.y), a1z = fabsf(v1.z), a1w = fabsf(v1.w);
    float a2x = fabsf(v2.x), a2y = fabsf(v2.y), a2z = fabsf(v2.z), a2w = fabsf(v2.w);
    float s0 = a0x + a0y + a0z + a0w;
    float s1 = a1x + a1y + a1z + a1w;
    float s2 = a2x + a2y + a2z + a2w;
    #pragma unroll
    for (int o = 16; o; o >>= 1) {
        s0 += __shfl_down_sync(0xffffffffu, s0, o);
        s1 += __shfl_down_sync(0xffffffffu, s1, o);
        s2 += __shfl_down_sync(0xffffffffu, s2, o);
    }
    if (lane == 0) { sh[0][w] = s0; sh[1][w] = s1; sh[2][w] = s2; }
    __syncthreads();
    float t0 = sh[0][0] + sh[0][1] + sh[0][2] + sh[0][3];
    float t1 = sh[1][0] + sh[1][1] + sh[1][2] + sh[1][3];
    float t2 = sh[2][0] + sh[2][1] + sh[2][2] + sh[2][3];
    float i0 = 1.0f / (t0 + EPSV), i1 = 1.0f / (t1 + EPSV), i2 = 1.0f / (t2 + EPSV);

    float e0, e1, e2;
    {
        float f0 = a0x * i0, f1 = a0y * i0, f2 = a0z * i0, f3 = a0w * i0;
        e0 = f0 * logf(f0 + EPSV) + f1 * logf(f1 + EPSV)
           + f2 * logf(f2 + EPSV) + f3 * logf(f3 + EPSV);
    }
    {
        float f0 = a1x * i1, f1 = a1y * i1, f2 = a1z * i1, f3 = a1w * i1;
        e1 = f0 * logf(f0 + EPSV) + f1 * logf(f1 + EPSV)
           + f2 * logf(f2 + EPSV) + f3 * logf(f3 + EPSV);
    }
    {
        float f0 = a2x * i2, f1 = a2y * i2, f2 = a2z * i2, f3 = a2w * i2;
        e2 = f0 * logf(f0 + EPSV) + f1 * logf(f1 + EPSV)
           + f2 * logf(f2 + EPSV) + f3 * logf(f3 + EPSV);
    }
    #pragma unroll
    for (int o = 16; o; o >>= 1) {
        e0 += __shfl_down_sync(0xffffffffu, e0, o);
        e1 += __shfl_down_sync(0xffffffffu, e1, o);
        e2 += __shfl_down_sync(0xffffffffu, e2, o);
    }
    __syncthreads();
    if (lane == 0) { sh[0][w] = e0; sh[1][w] = e1; sh[2][w] = e2; }
    __syncthreads();
    if (tid == 0) {
        g_ent[0 * MM + r] = -(sh[0][0] + sh[0][1] + sh[0][2] + sh[0][3]);
        g_ent[1 * MM + r] = -(sh[1][0] + sh[1][1] + sh[1][2] + sh[1][3]);
        g_ent[2 * MM + r] = -(sh[2][0] + sh[2][1] + sh[2][2] + sh[2][3]);
    }

    split4_store(v0, g_fh, g_fl, 0LL * MM * HH + off);
    split4_store(v1, g_fh, g_fl, 1LL * MM * HH + off);
    split4_store(v2, g_fh, g_fl, 2LL * MM * HH + off);
    float4 tq = make_float4(v0.x + v1.x + v2.x, v0.y + v1.y + v2.y,
                            v0.z + v1.z + v2.z, v0.w + v1.w + v2.w);
    split4_store(tq, g_toth, g_totl, off);
}

// ----------------------------------------------------------------------------
// Weight prep
// ----------------------------------------------------------------------------
__global__ void prep_weights(const float* __restrict__ gW) {
    int idx = blockIdx.x * blockDim.x + threadIdx.x;
    if (idx < HH * HH) {
        float wa = gW[idx];
        float wb = gW[HH * HH + idx];
        float wc = gW[2 * HH * HH + idx];
        float aw = wa + wb - 0.5f * wc;
        float wh = 0.5f * wc;
        __nv_bfloat16 h1 = __float2bfloat16(aw);
        g_Awh[idx] = h1; g_Awl[idx] = __float2bfloat16(aw - __bfloat162float(h1));
        __nv_bfloat16 h2 = __float2bfloat16(wh);
        g_Whh[idx] = h2; g_Whl[idx] = __float2bfloat16(wh - __bfloat162float(h2));
    }
    if (idx < HH) g_wlast[idx] = gW[3 * HH * HH + idx];
}

__global__ void conv_w(const float* __restrict__ src, __nv_bfloat16* __restrict__ h,
                       __nv_bfloat16* __restrict__ l, int n4) {
    int i = blockIdx.x * blockDim.x + threadIdx.x;
    if (i < n4) {
        float4 v = ((const float4*)src)[i];
        split4_store(v, h, l, (long long)i * 4);
    }
}

__global__ void transpose_wc(const float* __restrict__ Wc) {
    int idx = blockIdx.x * blockDim.x + threadIdx.x;
    if (idx < HH * CC) {
        int k = idx / CC, c = idx % CC;
        g_WcT[c * HH + k] = Wc[k * CC + c];
    }
}

// ----------------------------------------------------------------------------
// gate_fuse
// ----------------------------------------------------------------------------
__global__ void gate_fuse_kernel(const float* __restrict__ gate_b,
                                 const float* __restrict__ text,
                                 const float* __restrict__ audio,
                                 const float* __restrict__ visual) {
    long long r = blockIdx.x;
    int m = blockIdx.y;
    const float* feat = (m == 0) ? text : (m == 1) ? audio : visual;
    float e = g_ent[(long long)m * MM + r];
    int j = threadIdx.x * 4;
    long long gi = ((long long)m * MM + r) * HH + j;
    __nv_bfloat162 gh0 = *(const __nv_bfloat162*)(g_Gh + gi);
    __nv_bfloat162 gh1 = *(const __nv_bfloat162*)(g_Gh + gi + 2);
    __nv_bfloat162 gl0 = *(const __nv_bfloat162*)(g_Gl + gi);
    __nv_bfloat162 gl1 = *(const __nv_bfloat162*)(g_Gl + gi + 2);
    long long ti = r * HH + j;
    __nv_bfloat162 th0 = *(const __nv_bfloat162*)(g_Th + ti);
    __nv_bfloat162 th1 = *(const __nv_bfloat162*)(g_Th + ti + 2);
    __nv_bfloat162 tl0 = *(const __nv_bfloat162*)(g_Tl + ti);
    __nv_bfloat162 tl1 = *(const __nv_bfloat162*)(g_Tl + ti + 2);
    float4 wv = *(const float4*)(g_wlast + j);
    float4 bv = *(const float4*)(gate_b + j);
    float4 fv = *(const float4*)(feat + r * HH + j);

    float gx = __bfloat162float(gh0.x) + __bfloat162float(gl0.x);
    float gy = __bfloat162float(gh0.y) + __bfloat162float(gl0.y);
    float gz = __bfloat162float(gh1.x) + __bfloat162float(gl1.x);
    float gw = __bfloat162float(gh1.y) + __bfloat162float(gl1.y);
    float tx = __bfloat162float(th0.x) + __bfloat162float(tl0.x);
    float ty = __bfloat162float(th0.y) + __bfloat162float(tl0.y);
    float tz = __bfloat162float(th1.x) + __bfloat162float(tl1.x);
    float tw = __bfloat162float(th1.y) + __bfloat162float(tl1.y);

    float zx = gx + tx + e * wv.x + bv.x;
    float zy = gy + ty + e * wv.y + bv.y;
    float zz = gz + tz + e * wv.z + bv.z;
    float zw = gw + tw + e * wv.w + bv.w;
    float4 o;
    o.x = fv.x / (1.0f + expf(-zx));
    o.y = fv.y / (1.0f + expf(-zy));
    o.z = fv.z / (1.0f + expf(-zz));
    o.w = fv.w / (1.0f + expf(-zw));
    split4_store(o, g_h0h, g_h0l, r * H3 + m * HH + j);
}

// ----------------------------------------------------------------------------
// Degree + normalized adjacency
// ----------------------------------------------------------------------------
__global__ void degree_kernel(const float* __restrict__ sp, const float* __restrict__ tp) {
    __shared__ float sh[8];
    long long b = blockIdx.y, i = blockIdx.x;
    const float* rs = sp + (b * SS + i) * SS;
    const float* rt = tp + (b * SS + i) * SS;
    float s = 0.0f;
    for (int j = threadIdx.x; j < SS; j += 256) s += rs[j] + rt[j];
    #pragma unroll
    for (int o = 16; o; o >>= 1) s += __shfl_down_sync(0xffffffffu, s, o);
    int lane = threadIdx.x & 31, w = threadIdx.x >> 5;
    if (lane == 0) sh[w] = s;
    __syncthreads();
    if (threadIdx.x == 0) {
        float D = 1.0f + 0.5f * (sh[0] + sh[1] + sh[2] + sh[3] + sh[4] + sh[5] + sh[6] + sh[7]);
        g_dsi[b * SS + i] = 1.0f / sqrtf(D + EPSV);
    }
}

__global__ void normadj_kernel(const float* __restrict__ sp, const float* __restrict__ tp) {
    long long n4 = (long long)BB * SS * SS / 4;
    for (long long g = (long long)blockIdx.x * blockDim.x + threadIdx.x; g < n4;
         g += (long long)gridDim.x * blockDim.x) {
        long long e = g * 4;
        int b = (int)(e / ((long long)SS * SS));
        long long rrem = e % ((long long)SS * SS);
        int i = (int)(rrem / SS);
        int j = (int)(rrem % SS);
        float4 a = *(const float4*)(sp + e);
        float4 c = *(const float4*)(tp + e);
        float di = g_dsi[(long long)b * SS + i];
        const float* dj = g_dsi + (long long)b * SS + j;
        float4 o;
        o.x = (0.5f * (a.x + c.x) + (j + 0 == i ? 1.0f : 0.0f)) * di * dj[0];
        o.y = (0.5f * (a.y + c.y) + (j + 1 == i ? 1.0f : 0.0f)) * di * dj[1];
        o.z = (0.5f * (a.z + c.z) + (j + 2 == i ? 1.0f : 0.0f)) * di * dj[2];
        o.w = (0.5f * (a.w + c.w) + (j + 3 == i ? 1.0f : 0.0f)) * di * dj[3];
        split4_store(o, g_adjh, g_adjl, e);
    }
}

// ----------------------------------------------------------------------------
// Classifier
// ----------------------------------------------------------------------------
__global__ void classifier_kernel(const float* __restrict__ bc, float* __restrict__ out) {
    __shared__ float sh[HH];
    long long r = blockIdx.x;
    for (int k = threadIdx.x; k < HH; k += 224)
        sh[k] = __bfloat162float(g_hh[r * HH + k]) + __bfloat162float(g_hl[r * HH + k]);
    __syncthreads();
    int w = threadIdx.x >> 5, lane = threadIdx.x & 31;
    if (w < CC) {
        const float* wrow = g_WcT + w * HH;
        float s = 0.0f;
        #pragma unroll
        for (int k = lane; k < HH; k += 32) s += sh[k] * wrow[k];
        #pragma unroll
        for (int o = 16; o; o >>= 1) s += __shfl_down_sync(0xffffffffu, s, o);
        if (lane == 0) out[r * CC + w] = s + bc[w];
    }
}

// ----------------------------------------------------------------------------
// Launch  (order chosen so launch #5 — the ncu capture slot — is the big
// batched gating GEMM)
// ----------------------------------------------------------------------------
extern "C" void kernel_launch(void* const* d_in, const int* in_sizes, int n_in,
                              void* d_out, int out_size) {
    const float* text   = (const float*)d_in[0];
    const float* audio  = (const float*)d_in[1];
    const float* visual = (const float*)d_in[2];
    const float* sp     = (const float*)d_in[3];
    const float* tp     = (const float*)d_in[4];
    const float* gate_W = (const float*)d_in[6];
    const float* gate_b = (const float*)d_in[7];
    const float* W0 = (const float*)d_in[8];
    const float* b0 = (const float*)d_in[9];
    const float* W1 = (const float*)d_in[10];
    const float* b1 = (const float*)d_in[11];
    const float* W2 = (const float*)d_in[12];
    const float* b2 = (const float*)d_in[13];
    const float* Wc = (const float*)d_in[14];
    const float* bc = (const float*)d_in[15];
    float* out = (float*)d_out;

    static bool attr_done = false;
    if (!attr_done) {
        cudaFuncSetAttribute(mma_gemm<0>, cudaFuncAttributeMaxDynamicSharedMemorySize, SMEM_BYTES);
        cudaFuncSetAttribute(mma_gemm<1>, cudaFuncAttributeMaxDynamicSharedMemorySize, SMEM_BYTES);
        attr_done = true;
    }

    #define SYM(p, s) cudaGetSymbolAddress((void**)&p, s)
    __nv_bfloat16 *fh, *fl, *toth, *totl, *Gh, *Gl, *Th, *Tl, *h0h, *h0l;
    __nv_bfloat16 *adjh, *adjl, *tmph, *tmpl, *hh, *hl;
    __nv_bfloat16 *Awh, *Awl, *Whh, *Whl, *W0h, *W0l, *W1h, *W1l, *W2h, *W2l;
    SYM(fh, g_fh); SYM(fl, g_fl); SYM(toth, g_toth); SYM(totl, g_totl);
    SYM(Gh, g_Gh); SYM(Gl, g_Gl); SYM(Th, g_Th); SYM(Tl, g_Tl);
    SYM(h0h, g_h0h); SYM(h0l, g_h0l);
    SYM(adjh, g_adjh); SYM(adjl, g_adjl);
    SYM(tmph, g_tmph); SYM(tmpl, g_tmpl); SYM(hh, g_hh); SYM(hl, g_hl);
    SYM(Awh, g_Awh); SYM(Awl, g_Awl); SYM(Whh, g_Whh); SYM(Whl, g_Whl);
    SYM(W0h, g_W0h); SYM(W0l, g_W0l); SYM(W1h, g_W1h); SYM(W1l, g_W1l);
    SYM(W2h, g_W2h); SYM(W2l, g_W2l);
    #undef SYM

    long long sF = (long long)MM * HH;
    dim3 gemm_grid(HH / BN, MM / BM, 1);
    dim3 gate_grid(HH / BN, MM / BM, 3);
    dim3 adj_grid(HH / BN, SS / BM, BB);
    long long sAdj = (long long)SS * SS, sL = (long long)SS * HH;

    // launches 0-4: prep needed by the gating GEMM
    prep_weights<<<(HH * HH + 255) / 256, 256>>>(gate_W);                    // 0
    transpose_wc<<<(HH * CC + 255) / 256, 256>>>(Wc);                        // 1
    prep_feats<<<MM, 128>>>(text, audio, visual);                            // 2
    degree_kernel<<<dim3(SS, BB), 256>>>(sp, tp);                            // 3
    normadj_kernel<<<8192, 256>>>(sp, tp);                                   // 4

    // launch 5: batched gating GEMM  <-- ncu -s 5 -c 1 captures this
    mma_gemm<0><<<gate_grid, 256, SMEM_BYTES>>>(fh, fl, Awh, Awl, nullptr,
                                                Gh, Gl, MM, HH, HH, sF, 0, sF);
    mma_gemm<0><<<gemm_grid, 256, SMEM_BYTES>>>(toth, totl, Whh, Whl, nullptr,
                                                Th, Tl, MM, HH, HH, 0, 0, 0);
    gate_fuse_kernel<<<dim3(MM, 3), 128>>>(gate_b, text, audio, visual);

    // weight conversions for the GNN (independent of gating path)
    conv_w<<<(H3 * HH / 4 + 255) / 256, 256>>>(W0, W0h, W0l, H3 * HH / 4);
    conv_w<<<(HH * HH / 4 + 255) / 256, 256>>>(W1, W1h, W1l, HH * HH / 4);
    conv_w<<<(HH * HH / 4 + 255) / 256, 256>>>(W2, W2h, W2l, HH * HH / 4);

    // spectral GNN
    mma_gemm<0><<<gemm_grid, 256, SMEM_BYTES>>>(h0h, h0l, W0h, W0l, nullptr,
                                                tmph, tmpl, MM, HH, H3, 0, 0, 0);
    mma_gemm<1><<<adj_grid, 256, SMEM_BYTES>>>(adjh, adjl, tmph, tmpl, b0,
                                               hh, hl, SS, HH, SS, sAdj, sL, sL);

    mma_gemm<0><<<gemm_grid, 256, SMEM_BYTES>>>(hh, hl, W1h, W1l, nullptr,
                                                tmph, tmpl, MM, HH, HH, 0, 0, 0);
    mma_gemm<1><<<adj_grid, 256, SMEM_BYTES>>>(adjh, adjl, tmph, tmpl, b1,
                                               hh, hl, SS, HH, SS, sAdj, sL, sL);

    mma_gemm<0><<<gemm_grid, 256, SMEM_BYTES>>>(hh, hl, W2h, W2l, nullptr,
                                                tmph, tmpl, MM, HH, HH, 0, 0, 0);
    mma_gemm<1><<<adj_grid, 256, SMEM_BYTES>>>(adjh, adjl, tmph, tmpl, b2,
                                               hh, hl, SS, HH, SS, sAdj, sL, sL);

    // classifier
    classifier_kernel<<<MM, 224>>>(bc, out);
}

// round 8
// speedup vs baseline: 1.3563x; 1.3563x over previous
#include <cuda_runtime.h>
#include <cuda_fp16.h>
#include <cstdint>
#include <math.h>

// Problem dims (fixed by the dataset)
#define BB 16
#define SS 1024
#define HH 512
#define CC 7
#define MM (BB * SS)        // 16384 rows
#define H3 (3 * HH)         // 1536
#define EPSV 1e-10f

// GEMM tiling
#define BM 128
#define BN 128
#define BK 32
#define LDA 40              // halves, padded (80B rows: cp.async-aligned, ldmatrix conflict-free)
#define LDB 136             // halves, padded (272B rows)
#define NSTG 3
#define STAGE_H (2 * BM * LDA + 2 * BK * LDB)      // halves per stage = 18944
#define SMEM_BYTES (NSTG * STAGE_H * 2)            // 113664 B

// ----------------------------------------------------------------------------
// Static scratch (fp16 planes; no allocations anywhere)
// ----------------------------------------------------------------------------
__device__ __half g_fh[3 * MM * HH],  g_fl[3 * MM * HH];    // text/audio/visual hi/lo
__device__ __half g_toth[MM * HH],    g_totl[MM * HH];
__device__ __half g_Gh[3 * MM * HH],  g_Gl[3 * MM * HH];
__device__ __half g_Th[MM * HH],      g_Tl[MM * HH];
__device__ __half g_h0h[MM * H3],     g_h0l[MM * H3];
__device__ __half g_adj[BB * SS * SS];                      // single fp16
__device__ __half g_tmph[MM * HH],    g_tmpl[MM * HH];
__device__ __half g_hh[MM * HH],      g_hl[MM * HH];
__device__ __half g_Aw[HH * HH];                            // single fp16 weights
__device__ __half g_Wh[HH * HH];
__device__ __half g_W0[H3 * HH];
__device__ __half g_W1[HH * HH];
__device__ __half g_W2[HH * HH];
__device__ float g_ent[3 * MM];
__device__ float g_dsi[BB * SS];
__device__ float g_wlast[HH];
__device__ float g_WcT[CC * HH];

// ----------------------------------------------------------------------------
// Helpers
// ----------------------------------------------------------------------------
__device__ __forceinline__ unsigned s2u(const void* p) {
    return (unsigned)__cvta_generic_to_shared(p);
}

__device__ __forceinline__ void split4_store(float4 v, __half* h, __half* l,
                                             long long idx) {
    __half hx = __float2half_rn(v.x), hy = __float2half_rn(v.y);
    __half hz = __float2half_rn(v.z), hw = __float2half_rn(v.w);
    __half lx = __float2half_rn(v.x - __half2float(hx));
    __half ly = __float2half_rn(v.y - __half2float(hy));
    __half lz = __float2half_rn(v.z - __half2float(hz));
    __half lw = __float2half_rn(v.w - __half2float(hw));
    *(__half2*)(h + idx)     = __halves2half2(hx, hy);
    *(__half2*)(h + idx + 2) = __halves2half2(hz, hw);
    *(__half2*)(l + idx)     = __halves2half2(lx, ly);
    *(__half2*)(l + idx + 2) = __halves2half2(lz, lw);
}

__device__ __forceinline__ void store4h(float4 v, __half* p, long long idx) {
    *(__half2*)(p + idx)     = __halves2half2(__float2half_rn(v.x), __float2half_rn(v.y));
    *(__half2*)(p + idx + 2) = __halves2half2(__float2half_rn(v.z), __float2half_rn(v.w));
}

#define MMA16816(d, a, b)                                                  \
    asm volatile(                                                          \
        "mma.sync.aligned.m16n8k16.row.col.f32.f16.f16.f32 "               \
        "{%0,%1,%2,%3}, {%4,%5,%6,%7}, {%8,%9}, {%0,%1,%2,%3};\n"          \
        : "+f"(d[0]), "+f"(d[1]), "+f"(d[2]), "+f"(d[3])                   \
        : "r"(a[0]), "r"(a[1]), "r"(a[2]), "r"(a[3]), "r"(b[0]), "r"(b[1]))

#define LDSM_X4(r0, r1, r2, r3, addr)                                      \
    asm volatile("ldmatrix.sync.aligned.m8n8.x4.shared.b16 "               \
                 "{%0,%1,%2,%3}, [%4];\n"                                  \
                 : "=r"(r0), "=r"(r1), "=r"(r2), "=r"(r3) : "r"(addr))

#define LDSM_X4T(r0, r1, r2, r3, addr)                                     \
    asm volatile("ldmatrix.sync.aligned.m8n8.x4.trans.shared.b16 "         \
                 "{%0,%1,%2,%3}, [%4];\n"                                  \
                 : "=r"(r0), "=r"(r1), "=r"(r2), "=r"(r3) : "r"(addr))

#define CP16(dst, src)                                                     \
    asm volatile("cp.async.cg.shared.global [%0], [%1], 16;\n"             \
                 :: "r"(dst), "l"(src))
#define CP_COMMIT asm volatile("cp.async.commit_group;\n" ::: "memory")
#define CP_WAIT(n) asm volatile("cp.async.wait_group %0;\n" :: "n"(n) : "memory")

// ----------------------------------------------------------------------------
// fp16-split tensor-core GEMM, 3-stage cp.async pipeline, 2 MMAs per logical.
// SPLITA=1: A = hi/lo planes, B = single plane.   C = (Ah+Al) @ B
// SPLITA=0: A = single plane, B = hi/lo planes.   C = A @ (Bh+Bl)
// EPI: 0 = none, 1 = bias+relu. Output always hi/lo fp16 planes.
// ----------------------------------------------------------------------------
template <int EPI, int SPLITA>
__global__ void __launch_bounds__(256) mma_gemm(
    const __half* __restrict__ A0g, const __half* __restrict__ A1g,
    const __half* __restrict__ B0g, const __half* __restrict__ B1g,
    const float* __restrict__ bias,
    __half* __restrict__ Chg, __half* __restrict__ Clg,
    int M, int N, int K, long long sA, long long sB, long long sC)
{
    extern __shared__ __half sm[];
    // stage layout (halves): A0[0,5120) A1[5120,10240) B0[10240,14592) B1[14592,18944)

    const __half* A0 = A0g + (long long)blockIdx.z * sA;
    const __half* A1 = SPLITA ? (A1g + (long long)blockIdx.z * sA) : A0g;
    const __half* B0 = B0g + (long long)blockIdx.z * sB;
    const __half* B1 = SPLITA ? B0g : (B1g + (long long)blockIdx.z * sB);
    __half* Ch = Chg + (long long)blockIdx.z * sC;
    __half* Cl = Clg + (long long)blockIdx.z * sC;

    int t = threadIdx.x, lane = t & 31, wid = t >> 5;
    int warp_m = wid >> 2, warp_n = wid & 3;    // 2 x 4 warps
    int brow = blockIdx.y * BM, bcol = blockIdx.x * BN;
    int KT = K / BK;

    float acc[4][4][4];
    #pragma unroll
    for (int i = 0; i < 4; i++)
        #pragma unroll
        for (int j = 0; j < 4; j++)
            #pragma unroll
            for (int q = 0; q < 4; q++) acc[i][j][q] = 0.0f;

    // tile loader: 6x cp.async 16B per thread into stage s (3 planes)
    auto load_tile = [&](int kt, int s) {
        int k0 = kt * BK;
        __half* st = sm + s * STAGE_H;
        #pragma unroll
        for (int i = 0; i < 2; i++) {
            int q = t + i * 256;
            int ra = q >> 2, ca = (q & 3) << 3;         // A: 128 rows x 4 chunks
            long long asrc = (long long)(brow + ra) * K + k0 + ca;
            CP16(s2u(st + ra * LDA + ca), A0 + asrc);
            if (SPLITA)
                CP16(s2u(st + BM * LDA + ra * LDA + ca), A1 + asrc);
            int rb = q >> 4, cb = (q & 15) << 3;        // B: 32 rows x 16 chunks
            long long bsrc = (long long)(k0 + rb) * N + bcol + cb;
            CP16(s2u(st + 2 * BM * LDA + rb * LDB + cb), B0 + bsrc);
            if (!SPLITA)
                CP16(s2u(st + 2 * BM * LDA + BK * LDB + rb * LDB + cb), B1 + bsrc);
        }
    };

    load_tile(0, 0); CP_COMMIT;
    load_tile(1, 1); CP_COMMIT;

    int s = 0;
    for (int kt = 0; kt < KT; kt++) {
        if (kt + 2 < KT) { CP_WAIT(1); } else { CP_WAIT(0); }
        __syncthreads();

        if (kt + 2 < KT) { load_tile(kt + 2, (s + 2) % NSTG); CP_COMMIT; }

        const __half* cA0 = sm + s * STAGE_H;
        const __half* cA1 = cA0 + BM * LDA;
        const __half* cB0 = cA0 + 2 * BM * LDA;
        const __half* cB1 = cB0 + BK * LDB;

        #pragma unroll
        for (int kk = 0; kk < BK; kk += 16) {
            unsigned a0[4][4], a1[4][4], b0[4][2], b1[4][2];
            int arow = warp_m * 64 + (lane & 15);
            int acol = kk + ((lane >> 4) << 3);
            #pragma unroll
            for (int tm = 0; tm < 4; tm++) {
                LDSM_X4(a0[tm][0], a0[tm][1], a0[tm][2], a0[tm][3],
                        s2u(&cA0[(arow + tm * 16) * LDA + acol]));
                if (SPLITA)
                    LDSM_X4(a1[tm][0], a1[tm][1], a1[tm][2], a1[tm][3],
                            s2u(&cA1[(arow + tm * 16) * LDA + acol]));
            }
            int brow_ = kk + (lane & 15);
            #pragma unroll
            for (int tp = 0; tp < 2; tp++) {
                int bc = warp_n * 32 + tp * 16 + ((lane >> 4) << 3);
                LDSM_X4T(b0[2 * tp][0], b0[2 * tp][1],
                         b0[2 * tp + 1][0], b0[2 * tp + 1][1],
                         s2u(&cB0[brow_ * LDB + bc]));
                if (!SPLITA)
                    LDSM_X4T(b1[2 * tp][0], b1[2 * tp][1],
                             b1[2 * tp + 1][0], b1[2 * tp + 1][1],
                             s2u(&cB1[brow_ * LDB + bc]));
            }
            #pragma unroll
            for (int tm = 0; tm < 4; tm++)
                #pragma unroll
                for (int tn = 0; tn < 4; tn++) {
                    MMA16816(acc[tm][tn], a0[tm], b0[tn]);
                    if (SPLITA) { MMA16816(acc[tm][tn], a1[tm], b0[tn]); }
                    else        { MMA16816(acc[tm][tn], a0[tm], b1[tn]); }
                }
        }
        s = (s + 1) % NSTG;
    }

    // ---- epilogue: (bias+relu) then split to hi/lo fp16 planes ----
    int g = lane >> 2, tig = lane & 3;
    #pragma unroll
    for (int tm = 0; tm < 4; tm++)
        #pragma unroll
        for (int tn = 0; tn < 4; tn++) {
            int row = brow + warp_m * 64 + tm * 16 + g;
            int col = bcol + warp_n * 32 + tn * 8 + tig * 2;
            float2 v0 = make_float2(acc[tm][tn][0], acc[tm][tn][1]);
            float2 v1 = make_float2(acc[tm][tn][2], acc[tm][tn][3]);
            if (EPI == 1) {
                float b0v = bias[col], b1v = bias[col + 1];
                v0.x = fmaxf(v0.x + b0v, 0.0f); v0.y = fmaxf(v0.y + b1v, 0.0f);
                v1.x = fmaxf(v1.x + b0v, 0.0f); v1.y = fmaxf(v1.y + b1v, 0.0f);
            }
            #pragma unroll
            for (int rr = 0; rr < 2; rr++) {
                float2 v = rr ? v1 : v0;
                long long idx = (long long)(row + rr * 8) * N + col;
                __half h0 = __float2half_rn(v.x);
                __half h1 = __float2half_rn(v.y);
                __half l0 = __float2half_rn(v.x - __half2float(h0));
                __half l1 = __float2half_rn(v.y - __half2float(h1));
                *(__half2*)(Ch + idx) = __halves2half2(h0, h1);
                *(__half2*)(Cl + idx) = __halves2half2(l0, l1);
            }
        }
}

// ----------------------------------------------------------------------------
// Fused: entropy + fp16 split of feats + total
// ----------------------------------------------------------------------------
__global__ void prep_feats(const float* __restrict__ text,
                           const float* __restrict__ audio,
                           const float* __restrict__ visual) {
    __shared__ float sh[3][4];
    long long r = blockIdx.x;
    int tid = threadIdx.x, lane = tid & 31, w = tid >> 5;
    long long off = r * HH + tid * 4;
    float4 v0 = *(const float4*)(text + off);
    float4 v1 = *(const float4*)(audio + off);
    float4 v2 = *(const float4*)(visual + off);

    float a0x = fabsf(v0.x), a0y = fabsf(v0.y), a0z = fabsf(v0.z), a0w = fabsf(v0.w);
    float a1x = fabsf(v1.x), a1y = fabsf(v1.y), a1z = fabsf(v1.z), a1w = fabsf(v1.w);
    float a2x = fabsf(v2.x), a2y = fabsf(v2.y), a2z = fabsf(v2.z), a2w = fabsf(v2.w);
    float s0 = a0x + a0y + a0z + a0w;
    float s1 = a1x + a1y + a1z + a1w;
    float s2 = a2x + a2y + a2z + a2w;
    #pragma unroll
    for (int o = 16; o; o >>= 1) {
        s0 += __shfl_down_sync(0xffffffffu, s0, o);
        s1 += __shfl_down_sync(0xffffffffu, s1, o);
        s2 += __shfl_down_sync(0xffffffffu, s2, o);
    }
    if (lane == 0) { sh[0][w] = s0; sh[1][w] = s1; sh[2][w] = s2; }
    __syncthreads();
    float t0 = sh[0][0] + sh[0][1] + sh[0][2] + sh[0][3];
    float t1 = sh[1][0] + sh[1][1] + sh[1][2] + sh[1][3];
    float t2 = sh[2][0] + sh[2][1] + sh[2][2] + sh[2][3];
    float i0 = 1.0f / (t0 + EPSV), i1 = 1.0f / (t1 + EPSV), i2 = 1.0f / (t2 + EPSV);

    float e0, e1, e2;
    {
        float f0 = a0x * i0, f1 = a0y * i0, f2 = a0z * i0, f3 = a0w * i0;
        e0 = f0 * logf(f0 + EPSV) + f1 * logf(f1 + EPSV)
           + f2 * logf(f2 + EPSV) + f3 * logf(f3 + EPSV);
    }
    {
        float f0 = a1x * i1, f1 = a1y * i1, f2 = a1z * i1, f3 = a1w * i1;
        e1 = f0 * logf(f0 + EPSV) + f1 * logf(f1 + EPSV)
           + f2 * logf(f2 + EPSV) + f3 * logf(f3 + EPSV);
    }
    {
        float f0 = a2x * i2, f1 = a2y * i2, f2 = a2z * i2, f3 = a2w * i2;
        e2 = f0 * logf(f0 + EPSV) + f1 * logf(f1 + EPSV)
           + f2 * logf(f2 + EPSV) + f3 * logf(f3 + EPSV);
    }
    #pragma unroll
    for (int o = 16; o; o >>= 1) {
        e0 += __shfl_down_sync(0xffffffffu, e0, o);
        e1 += __shfl_down_sync(0xffffffffu, e1, o);
        e2 += __shfl_down_sync(0xffffffffu, e2, o);
    }
    __syncthreads();
    if (lane == 0) { sh[0][w] = e0; sh[1][w] = e1; sh[2][w] = e2; }
    __syncthreads();
    if (tid == 0) {
        g_ent[0 * MM + r] = -(sh[0][0] + sh[0][1] + sh[0][2] + sh[0][3]);
        g_ent[1 * MM + r] = -(sh[1][0] + sh[1][1] + sh[1][2] + sh[1][3]);
        g_ent[2 * MM + r] = -(sh[2][0] + sh[2][1] + sh[2][2] + sh[2][3]);
    }

    split4_store(v0, g_fh, g_fl, 0LL * MM * HH + off);
    split4_store(v1, g_fh, g_fl, 1LL * MM * HH + off);
    split4_store(v2, g_fh, g_fl, 2LL * MM * HH + off);
    float4 tq = make_float4(v0.x + v1.x + v2.x, v0.y + v1.y + v2.y,
                            v0.z + v1.z + v2.z, v0.w + v1.w + v2.w);
    split4_store(tq, g_toth, g_totl, off);
}

// ----------------------------------------------------------------------------
// Weight prep (single fp16 planes)
// ----------------------------------------------------------------------------
__global__ void prep_weights(const float* __restrict__ gW) {
    int idx = blockIdx.x * blockDim.x + threadIdx.x;
    if (idx < HH * HH) {
        float wa = gW[idx];
        float wb = gW[HH * HH + idx];
        float wc = gW[2 * HH * HH + idx];
        g_Aw[idx] = __float2half_rn(wa + wb - 0.5f * wc);
        g_Wh[idx] = __float2half_rn(0.5f * wc);
    }
    if (idx < HH) g_wlast[idx] = gW[3 * HH * HH + idx];
}

__global__ void conv_w(const float* __restrict__ src, __half* __restrict__ dst, int n4) {
    int i = blockIdx.x * blockDim.x + threadIdx.x;
    if (i < n4) {
        float4 v = ((const float4*)src)[i];
        store4h(v, dst, (long long)i * 4);
    }
}

__global__ void transpose_wc(const float* __restrict__ Wc) {
    int idx = blockIdx.x * blockDim.x + threadIdx.x;
    if (idx < HH * CC) {
        int k = idx / CC, c = idx % CC;
        g_WcT[c * HH + k] = Wc[k * CC + c];
    }
}

// ----------------------------------------------------------------------------
// gate_fuse: h0 = sigmoid(G + T + ent*wlast + gate_b) * feat -> hi/lo planes
// ----------------------------------------------------------------------------
__global__ void gate_fuse_kernel(const float* __restrict__ gate_b,
                                 const float* __restrict__ text,
                                 const float* __restrict__ audio,
                                 const float* __restrict__ visual) {
    long long r = blockIdx.x;
    int m = blockIdx.y;
    const float* feat = (m == 0) ? text : (m == 1) ? audio : visual;
    float e = g_ent[(long long)m * MM + r];
    int j = threadIdx.x * 4;
    long long gi = ((long long)m * MM + r) * HH + j;
    float2 gh0 = __half22float2(*(const __half2*)(g_Gh + gi));
    float2 gh1 = __half22float2(*(const __half2*)(g_Gh + gi + 2));
    float2 gl0 = __half22float2(*(const __half2*)(g_Gl + gi));
    float2 gl1 = __half22float2(*(const __half2*)(g_Gl + gi + 2));
    long long ti = r * HH + j;
    float2 th0 = __half22float2(*(const __half2*)(g_Th + ti));
    float2 th1 = __half22float2(*(const __half2*)(g_Th + ti + 2));
    float2 tl0 = __half22float2(*(const __half2*)(g_Tl + ti));
    float2 tl1 = __half22float2(*(const __half2*)(g_Tl + ti + 2));
    float4 wv = *(const float4*)(g_wlast + j);
    float4 bv = *(const float4*)(gate_b + j);
    float4 fv = *(const float4*)(feat + r * HH + j);

    float zx = (gh0.x + gl0.x) + (th0.x + tl0.x) + e * wv.x + bv.x;
    float zy = (gh0.y + gl0.y) + (th0.y + tl0.y) + e * wv.y + bv.y;
    float zz = (gh1.x + gl1.x) + (th1.x + tl1.x) + e * wv.z + bv.z;
    float zw = (gh1.y + gl1.y) + (th1.y + tl1.y) + e * wv.w + bv.w;
    float4 o;
    o.x = fv.x / (1.0f + expf(-zx));
    o.y = fv.y / (1.0f + expf(-zy));
    o.z = fv.z / (1.0f + expf(-zz));
    o.w = fv.w / (1.0f + expf(-zw));
    split4_store(o, g_h0h, g_h0l, r * H3 + m * HH + j);
}

// ----------------------------------------------------------------------------
// Degree + normalized adjacency (single fp16 plane)
// ----------------------------------------------------------------------------
__global__ void degree_kernel(const float* __restrict__ sp, const float* __restrict__ tp) {
    __shared__ float sh[8];
    long long b = blockIdx.y, i = blockIdx.x;
    const float* rs = sp + (b * SS + i) * SS;
    const float* rt = tp + (b * SS + i) * SS;
    float s = 0.0f;
    for (int j = threadIdx.x; j < SS; j += 256) s += rs[j] + rt[j];
    #pragma unroll
    for (int o = 16; o; o >>= 1) s += __shfl_down_sync(0xffffffffu, s, o);
    int lane = threadIdx.x & 31, w = threadIdx.x >> 5;
    if (lane == 0) sh[w] = s;
    __syncthreads();
    if (threadIdx.x == 0) {
        float D = 1.0f + 0.5f * (sh[0] + sh[1] + sh[2] + sh[3] + sh[4] + sh[5] + sh[6] + sh[7]);
        g_dsi[b * SS + i] = 1.0f / sqrtf(D + EPSV);
    }
}

__global__ void normadj_kernel(const float* __restrict__ sp, const float* __restrict__ tp) {
    long long n4 = (long long)BB * SS * SS / 4;
    for (long long g = (long long)blockIdx.x * blockDim.x + threadIdx.x; g < n4;
         g += (long long)gridDim.x * blockDim.x) {
        long long e = g * 4;
        int b = (int)(e / ((long long)SS * SS));
        long long rrem = e % ((long long)SS * SS);
        int i = (int)(rrem / SS);
        int j = (int)(rrem % SS);
        float4 a = *(const float4*)(sp + e);
        float4 c = *(const float4*)(tp + e);
        float di = g_dsi[(long long)b * SS + i];
        const float* dj = g_dsi + (long long)b * SS + j;
        float4 o;
        o.x = (0.5f * (a.x + c.x) + (j + 0 == i ? 1.0f : 0.0f)) * di * dj[0];
        o.y = (0.5f * (a.y + c.y) + (j + 1 == i ? 1.0f : 0.0f)) * di * dj[1];
        o.z = (0.5f * (a.z + c.z) + (j + 2 == i ? 1.0f : 0.0f)) * di * dj[2];
        o.w = (0.5f * (a.w + c.w) + (j + 3 == i ? 1.0f : 0.0f)) * di * dj[3];
        store4h(o, g_adj, e);
    }
}

// ----------------------------------------------------------------------------
// Classifier
// ----------------------------------------------------------------------------
__global__ void classifier_kernel(const float* __restrict__ bc, float* __restrict__ out) {
    __shared__ float sh[HH];
    long long r = blockIdx.x;
    for (int k = threadIdx.x; k < HH; k += 224)
        sh[k] = __half2float(g_hh[r * HH + k]) + __half2float(g_hl[r * HH + k]);
    __syncthreads();
    int w = threadIdx.x >> 5, lane = threadIdx.x & 31;
    if (w < CC) {
        const float* wrow = g_WcT + w * HH;
        float s = 0.0f;
        #pragma unroll
        for (int k = lane; k < HH; k += 32) s += sh[k] * wrow[k];
        #pragma unroll
        for (int o = 16; o; o >>= 1) s += __shfl_down_sync(0xffffffffu, s, o);
        if (lane == 0) out[r * CC + w] = s + bc[w];
    }
}

// ----------------------------------------------------------------------------
// Launch (launch #5 = batched gating GEMM, for ncu -s 5 -c 1)
// ----------------------------------------------------------------------------
extern "C" void kernel_launch(void* const* d_in, const int* in_sizes, int n_in,
                              void* d_out, int out_size) {
    const float* text   = (const float*)d_in[0];
    const float* audio  = (const float*)d_in[1];
    const float* visual = (const float*)d_in[2];
    const float* sp     = (const float*)d_in[3];
    const float* tp     = (const float*)d_in[4];
    const float* gate_W = (const float*)d_in[6];
    const float* gate_b = (const float*)d_in[7];
    const float* W0 = (const float*)d_in[8];
    const float* b0 = (const float*)d_in[9];
    const float* W1 = (const float*)d_in[10];
    const float* b1 = (const float*)d_in[11];
    const float* W2 = (const float*)d_in[12];
    const float* b2 = (const float*)d_in[13];
    const float* Wc = (const float*)d_in[14];
    const float* bc = (const float*)d_in[15];
    float* out = (float*)d_out;

    static bool attr_done = false;
    if (!attr_done) {
        cudaFuncSetAttribute(mma_gemm<0, 1>, cudaFuncAttributeMaxDynamicSharedMemorySize, SMEM_BYTES);
        cudaFuncSetAttribute(mma_gemm<1, 0>, cudaFuncAttributeMaxDynamicSharedMemorySize, SMEM_BYTES);
        attr_done = true;
    }

    #define SYM(p, s) cudaGetSymbolAddress((void**)&p, s)
    __half *fh, *fl, *toth, *totl, *Gh, *Gl, *Th, *Tl, *h0h, *h0l;
    __half *adj, *tmph, *tmpl, *hh, *hl;
    __half *Aw, *Wh, *W0p, *W1p, *W2p;
    SYM(fh, g_fh); SYM(fl, g_fl); SYM(toth, g_toth); SYM(totl, g_totl);
    SYM(Gh, g_Gh); SYM(Gl, g_Gl); SYM(Th, g_Th); SYM(Tl, g_Tl);
    SYM(h0h, g_h0h); SYM(h0l, g_h0l);
    SYM(adj, g_adj);
    SYM(tmph, g_tmph); SYM(tmpl, g_tmpl); SYM(hh, g_hh); SYM(hl, g_hl);
    SYM(Aw, g_Aw); SYM(Wh, g_Wh);
    SYM(W0p, g_W0); SYM(W1p, g_W1); SYM(W2p, g_W2);
    #undef SYM

    long long sF = (long long)MM * HH;
    dim3 gemm_grid(HH / BN, MM / BM, 1);
    dim3 gate_grid(HH / BN, MM / BM, 3);
    dim3 adj_grid(HH / BN, SS / BM, BB);
    long long sAdj = (long long)SS * SS, sL = (long long)SS * HH;

    // launches 0-4: prep needed by the gating GEMM
    prep_weights<<<(HH * HH + 255) / 256, 256>>>(gate_W);                    // 0
    transpose_wc<<<(HH * CC + 255) / 256, 256>>>(Wc);                        // 1
    prep_feats<<<MM, 128>>>(text, audio, visual);                            // 2
    degree_kernel<<<dim3(SS, BB), 256>>>(sp, tp);                            // 3
    normadj_kernel<<<8192, 256>>>(sp, tp);                                   // 4

    // launch 5: batched gating GEMM  <-- ncu -s 5 -c 1 captures this
    mma_gemm<0, 1><<<gate_grid, 256, SMEM_BYTES>>>(fh, fl, Aw, nullptr, nullptr,
                                                   Gh, Gl, MM, HH, HH, sF, 0, sF);
    mma_gemm<0, 1><<<gemm_grid, 256, SMEM_BYTES>>>(toth, totl, Wh, nullptr, nullptr,
                                                   Th, Tl, MM, HH, HH, 0, 0, 0);
    gate_fuse_kernel<<<dim3(MM, 3), 128>>>(gate_b, text, audio, visual);

    // weight conversions for the GNN
    conv_w<<<(H3 * HH / 4 + 255) / 256, 256>>>(W0, W0p, H3 * HH / 4);
    conv_w<<<(HH * HH / 4 + 255) / 256, 256>>>(W1, W1p, HH * HH / 4);
    conv_w<<<(HH * HH / 4 + 255) / 256, 256>>>(W2, W2p, HH * HH / 4);

    // spectral GNN
    mma_gemm<0, 1><<<gemm_grid, 256, SMEM_BYTES>>>(h0h, h0l, W0p, nullptr, nullptr,
                                                   tmph, tmpl, MM, HH, H3, 0, 0, 0);
    mma_gemm<1, 0><<<adj_grid, 256, SMEM_BYTES>>>(adj, nullptr, tmph, tmpl, b0,
                                                  hh, hl, SS, HH, SS, sAdj, sL, sL);

    mma_gemm<0, 1><<<gemm_grid, 256, SMEM_BYTES>>>(hh, hl, W1p, nullptr, nullptr,
                                                   tmph, tmpl, MM, HH, HH, 0, 0, 0);
    mma_gemm<1, 0><<<adj_grid, 256, SMEM_BYTES>>>(adj, nullptr, tmph, tmpl, b1,
                                                  hh, hl, SS, HH, SS, sAdj, sL, sL);

    mma_gemm<0, 1><<<gemm_grid, 256, SMEM_BYTES>>>(hh, hl, W2p, nullptr, nullptr,
                                                   tmph, tmpl, MM, HH, HH, 0, 0, 0);
    mma_gemm<1, 0><<<adj_grid, 256, SMEM_BYTES>>>(adj, nullptr, tmph, tmpl, b2,
                                                  hh, hl, SS, HH, SS, sAdj, sL, sL);

    // classifier
    classifier_kernel<<<MM, 224>>>(bc, out);
}

// round 9
// speedup vs baseline: 1.8291x; 1.3486x over previous
#include <cuda_runtime.h>
#include <cuda_fp16.h>
#include <cstdint>
#include <math.h>

// Problem dims (fixed by the dataset)
#define BB 16
#define SS 1024
#define HH 512
#define CC 7
#define MM (BB * SS)        // 16384 rows
#define H3 (3 * HH)         // 1536
#define EPSV 1e-10f

// GEMM tiling
#define BM 128
#define BN 128
#define BK 32
#define LDA 40              // halves, padded (80B rows: cp.async-aligned, ldmatrix conflict-free)
#define LDB 136             // halves, padded (272B rows)
#define NSTG 3
#define STAGE_H (2 * BM * LDA + BK * LDB)          // halves per stage = 14592
#define SMEM_BYTES (NSTG * STAGE_H * 2)            // 87552 B

// ----------------------------------------------------------------------------
// Static scratch (fp16 planes; no allocations anywhere)
// ----------------------------------------------------------------------------
__device__ __half g_f[3 * MM * HH];                         // text/audio/visual (single)
__device__ __half g_tot[MM * HH];
__device__ __half g_G[3 * MM * HH];                         // gating GEMM out (single)
__device__ __half g_T[MM * HH];
__device__ __half g_h0h[MM * H3],     g_h0l[MM * H3];       // gated features hi/lo
__device__ __half g_adj[BB * SS * SS];                      // single fp16
__device__ __half g_tmp[MM * HH];                           // feature GEMM out (single)
__device__ __half g_hh[MM * HH],      g_hl[MM * HH];        // layer act hi/lo
__device__ __half g_Aw[HH * HH];                            // single fp16 weights
__device__ __half g_Wh[HH * HH];
__device__ __half g_W0[H3 * HH];
__device__ __half g_W1[HH * HH];
__device__ __half g_W2[HH * HH];
__device__ float g_ent[3 * MM];
__device__ float g_dsi[BB * SS];
__device__ float g_wlast[HH];
__device__ float g_WcT[CC * HH];

// ----------------------------------------------------------------------------
// Helpers
// ----------------------------------------------------------------------------
__device__ __forceinline__ unsigned s2u(const void* p) {
    return (unsigned)__cvta_generic_to_shared(p);
}

__device__ __forceinline__ void split4_store(float4 v, __half* h, __half* l,
                                             long long idx) {
    __half hx = __float2half_rn(v.x), hy = __float2half_rn(v.y);
    __half hz = __float2half_rn(v.z), hw = __float2half_rn(v.w);
    __half lx = __float2half_rn(v.x - __half2float(hx));
    __half ly = __float2half_rn(v.y - __half2float(hy));
    __half lz = __float2half_rn(v.z - __half2float(hz));
    __half lw = __float2half_rn(v.w - __half2float(hw));
    *(__half2*)(h + idx)     = __halves2half2(hx, hy);
    *(__half2*)(h + idx + 2) = __halves2half2(hz, hw);
    *(__half2*)(l + idx)     = __halves2half2(lx, ly);
    *(__half2*)(l + idx + 2) = __halves2half2(lz, lw);
}

__device__ __forceinline__ void store4h(float4 v, __half* p, long long idx) {
    *(__half2*)(p + idx)     = __halves2half2(__float2half_rn(v.x), __float2half_rn(v.y));
    *(__half2*)(p + idx + 2) = __halves2half2(__float2half_rn(v.z), __float2half_rn(v.w));
}

#define MMA16816(d, a, b)                                                  \
    asm volatile(                                                          \
        "mma.sync.aligned.m16n8k16.row.col.f32.f16.f16.f32 "               \
        "{%0,%1,%2,%3}, {%4,%5,%6,%7}, {%8,%9}, {%0,%1,%2,%3};\n"          \
        : "+f"(d[0]), "+f"(d[1]), "+f"(d[2]), "+f"(d[3])                   \
        : "r"(a[0]), "r"(a[1]), "r"(a[2]), "r"(a[3]), "r"(b[0]), "r"(b[1]))

#define LDSM_X4(r0, r1, r2, r3, addr)                                      \
    asm volatile("ldmatrix.sync.aligned.m8n8.x4.shared.b16 "               \
                 "{%0,%1,%2,%3}, [%4];\n"                                  \
                 : "=r"(r0), "=r"(r1), "=r"(r2), "=r"(r3) : "r"(addr))

#define LDSM_X4T(r0, r1, r2, r3, addr)                                     \
    asm volatile("ldmatrix.sync.aligned.m8n8.x4.trans.shared.b16 "         \
                 "{%0,%1,%2,%3}, [%4];\n"                                  \
                 : "=r"(r0), "=r"(r1), "=r"(r2), "=r"(r3) : "r"(addr))

#define CP16(dst, src)                                                     \
    asm volatile("cp.async.cg.shared.global [%0], [%1], 16;\n"             \
                 :: "r"(dst), "l"(src))
#define CP_COMMIT asm volatile("cp.async.commit_group;\n" ::: "memory")
#define CP_WAIT(n) asm volatile("cp.async.wait_group %0;\n" :: "n"(n) : "memory")

// ----------------------------------------------------------------------------
// fp16 tensor-core GEMM, 3-stage cp.async pipeline.
// MODE 0: A = hi/lo planes (2 MMAs), B single.     C = (A0+A1) @ B
// MODE 1: A single, B single (1 MMA).              C = A @ B
// EPI: 0 = none, 1 = bias+relu.
// OSPLIT: 1 = write hi/lo planes, 0 = single plane.
// ----------------------------------------------------------------------------
template <int EPI, int MODE, int OSPLIT>
__global__ void __launch_bounds__(256) mma_gemm(
    const __half* __restrict__ A0g, const __half* __restrict__ A1g,
    const __half* __restrict__ B0g,
    const float* __restrict__ bias,
    __half* __restrict__ Chg, __half* __restrict__ Clg,
    int M, int N, int K, long long sA, long long sB, long long sC)
{
    extern __shared__ __half sm[];
    // stage layout (halves): A0[0,5120) A1[5120,10240) B0[10240,14592)

    const __half* A0 = A0g + (long long)blockIdx.z * sA;
    const __half* A1 = (MODE == 0) ? (A1g + (long long)blockIdx.z * sA) : A0g;
    const __half* B0 = B0g + (long long)blockIdx.z * sB;
    __half* Ch = Chg + (long long)blockIdx.z * sC;
    __half* Cl = OSPLIT ? (Clg + (long long)blockIdx.z * sC) : Chg;

    int t = threadIdx.x, lane = t & 31, wid = t >> 5;
    int warp_m = wid >> 2, warp_n = wid & 3;    // 2 x 4 warps
    int brow = blockIdx.y * BM, bcol = blockIdx.x * BN;
    int KT = K / BK;

    float acc[4][4][4];
    #pragma unroll
    for (int i = 0; i < 4; i++)
        #pragma unroll
        for (int j = 0; j < 4; j++)
            #pragma unroll
            for (int q = 0; q < 4; q++) acc[i][j][q] = 0.0f;

    auto load_tile = [&](int kt, int s) {
        int k0 = kt * BK;
        __half* st = sm + s * STAGE_H;
        #pragma unroll
        for (int i = 0; i < 2; i++) {
            int q = t + i * 256;
            int ra = q >> 2, ca = (q & 3) << 3;         // A: 128 rows x 4 chunks
            long long asrc = (long long)(brow + ra) * K + k0 + ca;
            CP16(s2u(st + ra * LDA + ca), A0 + asrc);
            if (MODE == 0)
                CP16(s2u(st + BM * LDA + ra * LDA + ca), A1 + asrc);
            int rb = q >> 4, cb = (q & 15) << 3;        // B: 32 rows x 16 chunks
            long long bsrc = (long long)(k0 + rb) * N + bcol + cb;
            CP16(s2u(st + 2 * BM * LDA + rb * LDB + cb), B0 + bsrc);
        }
    };

    load_tile(0, 0); CP_COMMIT;
    load_tile(1, 1); CP_COMMIT;

    int s = 0;
    for (int kt = 0; kt < KT; kt++) {
        if (kt + 2 < KT) { CP_WAIT(1); } else { CP_WAIT(0); }
        __syncthreads();

        if (kt + 2 < KT) { load_tile(kt + 2, (s + 2) % NSTG); CP_COMMIT; }

        const __half* cA0 = sm + s * STAGE_H;
        const __half* cA1 = cA0 + BM * LDA;
        const __half* cB0 = cA0 + 2 * BM * LDA;

        #pragma unroll
        for (int kk = 0; kk < BK; kk += 16) {
            unsigned a0[4][4], a1[4][4], b0[4][2];
            int arow = warp_m * 64 + (lane & 15);
            int acol = kk + ((lane >> 4) << 3);
            #pragma unroll
            for (int tm = 0; tm < 4; tm++) {
                LDSM_X4(a0[tm][0], a0[tm][1], a0[tm][2], a0[tm][3],
                        s2u(&cA0[(arow + tm * 16) * LDA + acol]));
                if (MODE == 0)
                    LDSM_X4(a1[tm][0], a1[tm][1], a1[tm][2], a1[tm][3],
                            s2u(&cA1[(arow + tm * 16) * LDA + acol]));
            }
            int brow_ = kk + (lane & 15);
            #pragma unroll
            for (int tp = 0; tp < 2; tp++) {
                int bc = warp_n * 32 + tp * 16 + ((lane >> 4) << 3);
                LDSM_X4T(b0[2 * tp][0], b0[2 * tp][1],
                         b0[2 * tp + 1][0], b0[2 * tp + 1][1],
                         s2u(&cB0[brow_ * LDB + bc]));
            }
            #pragma unroll
            for (int tm = 0; tm < 4; tm++)
                #pragma unroll
                for (int tn = 0; tn < 4; tn++) {
                    MMA16816(acc[tm][tn], a0[tm], b0[tn]);
                    if (MODE == 0) MMA16816(acc[tm][tn], a1[tm], b0[tn]);
                }
        }
        s = (s + 1) % NSTG;
    }

    // ---- epilogue ----
    int g = lane >> 2, tig = lane & 3;
    #pragma unroll
    for (int tm = 0; tm < 4; tm++)
        #pragma unroll
        for (int tn = 0; tn < 4; tn++) {
            int row = brow + warp_m * 64 + tm * 16 + g;
            int col = bcol + warp_n * 32 + tn * 8 + tig * 2;
            float2 v0 = make_float2(acc[tm][tn][0], acc[tm][tn][1]);
            float2 v1 = make_float2(acc[tm][tn][2], acc[tm][tn][3]);
            if (EPI == 1) {
                float b0v = bias[col], b1v = bias[col + 1];
                v0.x = fmaxf(v0.x + b0v, 0.0f); v0.y = fmaxf(v0.y + b1v, 0.0f);
                v1.x = fmaxf(v1.x + b0v, 0.0f); v1.y = fmaxf(v1.y + b1v, 0.0f);
            }
            #pragma unroll
            for (int rr = 0; rr < 2; rr++) {
                float2 v = rr ? v1 : v0;
                long long idx = (long long)(row + rr * 8) * N + col;
                __half h0 = __float2half_rn(v.x);
                __half h1 = __float2half_rn(v.y);
                *(__half2*)(Ch + idx) = __halves2half2(h0, h1);
                if (OSPLIT) {
                    __half l0 = __float2half_rn(v.x - __half2float(h0));
                    __half l1 = __float2half_rn(v.y - __half2float(h1));
                    *(__half2*)(Cl + idx) = __halves2half2(l0, l1);
                }
            }
        }
}

// ----------------------------------------------------------------------------
// Fused: entropy + fp16 convert of feats + total
// ----------------------------------------------------------------------------
__global__ void prep_feats(const float* __restrict__ text,
                           const float* __restrict__ audio,
                           const float* __restrict__ visual) {
    __shared__ float sh[3][4];
    long long r = blockIdx.x;
    int tid = threadIdx.x, lane = tid & 31, w = tid >> 5;
    long long off = r * HH + tid * 4;
    float4 v0 = *(const float4*)(text + off);
    float4 v1 = *(const float4*)(audio + off);
    float4 v2 = *(const float4*)(visual + off);

    float a0x = fabsf(v0.x), a0y = fabsf(v0.y), a0z = fabsf(v0.z), a0w = fabsf(v0.w);
    float a1x = fabsf(v1.x), a1y = fabsf(v1.y), a1z = fabsf(v1.z), a1w = fabsf(v1.w);
    float a2x = fabsf(v2.x), a2y = fabsf(v2.y), a2z = fabsf(v2.z), a2w = fabsf(v2.w);
    float s0 = a0x + a0y + a0z + a0w;
    float s1 = a1x + a1y + a1z + a1w;
    float s2 = a2x + a2y + a2z + a2w;
    #pragma unroll
    for (int o = 16; o; o >>= 1) {
        s0 += __shfl_down_sync(0xffffffffu, s0, o);
        s1 += __shfl_down_sync(0xffffffffu, s1, o);
        s2 += __shfl_down_sync(0xffffffffu, s2, o);
    }
    if (lane == 0) { sh[0][w] = s0; sh[1][w] = s1; sh[2][w] = s2; }
    __syncthreads();
    float t0 = sh[0][0] + sh[0][1] + sh[0][2] + sh[0][3];
    float t1 = sh[1][0] + sh[1][1] + sh[1][2] + sh[1][3];
    float t2 = sh[2][0] + sh[2][1] + sh[2][2] + sh[2][3];
    float i0 = 1.0f / (t0 + EPSV), i1 = 1.0f / (t1 + EPSV), i2 = 1.0f / (t2 + EPSV);

    float e0, e1, e2;
    {
        float f0 = a0x * i0, f1 = a0y * i0, f2 = a0z * i0, f3 = a0w * i0;
        e0 = f0 * logf(f0 + EPSV) + f1 * logf(f1 + EPSV)
           + f2 * logf(f2 + EPSV) + f3 * logf(f3 + EPSV);
    }
    {
        float f0 = a1x * i1, f1 = a1y * i1, f2 = a1z * i1, f3 = a1w * i1;
        e1 = f0 * logf(f0 + EPSV) + f1 * logf(f1 + EPSV)
           + f2 * logf(f2 + EPSV) + f3 * logf(f3 + EPSV);
    }
    {
        float f0 = a2x * i2, f1 = a2y * i2, f2 = a2z * i2, f3 = a2w * i2;
        e2 = f0 * logf(f0 + EPSV) + f1 * logf(f1 + EPSV)
           + f2 * logf(f2 + EPSV) + f3 * logf(f3 + EPSV);
    }
    #pragma unroll
    for (int o = 16; o; o >>= 1) {
        e0 += __shfl_down_sync(0xffffffffu, e0, o);
        e1 += __shfl_down_sync(0xffffffffu, e1, o);
        e2 += __shfl_down_sync(0xffffffffu, e2, o);
    }
    __syncthreads();
    if (lane == 0) { sh[0][w] = e0; sh[1][w] = e1; sh[2][w] = e2; }
    __syncthreads();
    if (tid == 0) {
        g_ent[0 * MM + r] = -(sh[0][0] + sh[0][1] + sh[0][2] + sh[0][3]);
        g_ent[1 * MM + r] = -(sh[1][0] + sh[1][1] + sh[1][2] + sh[1][3]);
        g_ent[2 * MM + r] = -(sh[2][0] + sh[2][1] + sh[2][2] + sh[2][3]);
    }

    store4h(v0, g_f, 0LL * MM * HH + off);
    store4h(v1, g_f, 1LL * MM * HH + off);
    store4h(v2, g_f, 2LL * MM * HH + off);
    float4 tq = make_float4(v0.x + v1.x + v2.x, v0.y + v1.y + v2.y,
                            v0.z + v1.z + v2.z, v0.w + v1.w + v2.w);
    store4h(tq, g_tot, off);
}

// ----------------------------------------------------------------------------
// Weight prep (single fp16 planes)
// ----------------------------------------------------------------------------
__global__ void prep_weights(const float* __restrict__ gW) {
    int idx = blockIdx.x * blockDim.x + threadIdx.x;
    if (idx < HH * HH) {
        float wa = gW[idx];
        float wb = gW[HH * HH + idx];
        float wc = gW[2 * HH * HH + idx];
        g_Aw[idx] = __float2half_rn(wa + wb - 0.5f * wc);
        g_Wh[idx] = __float2half_rn(0.5f * wc);
    }
    if (idx < HH) g_wlast[idx] = gW[3 * HH * HH + idx];
}

__global__ void conv_w(const float* __restrict__ src, __half* __restrict__ dst, int n4) {
    int i = blockIdx.x * blockDim.x + threadIdx.x;
    if (i < n4) {
        float4 v = ((const float4*)src)[i];
        store4h(v, dst, (long long)i * 4);
    }
}

__global__ void transpose_wc(const float* __restrict__ Wc) {
    int idx = blockIdx.x * blockDim.x + threadIdx.x;
    if (idx < HH * CC) {
        int k = idx / CC, c = idx % CC;
        g_WcT[c * HH + k] = Wc[k * CC + c];
    }
}

// ----------------------------------------------------------------------------
// gate_fuse: h0 = sigmoid(G + T + ent*wlast + gate_b) * feat -> hi/lo planes
// ----------------------------------------------------------------------------
__global__ void gate_fuse_kernel(const float* __restrict__ gate_b,
                                 const float* __restrict__ text,
                                 const float* __restrict__ audio,
                                 const float* __restrict__ visual) {
    long long r = blockIdx.x;
    int m = blockIdx.y;
    const float* feat = (m == 0) ? text : (m == 1) ? audio : visual;
    float e = g_ent[(long long)m * MM + r];
    int j = threadIdx.x * 4;
    long long gi = ((long long)m * MM + r) * HH + j;
    float2 gv0 = __half22float2(*(const __half2*)(g_G + gi));
    float2 gv1 = __half22float2(*(const __half2*)(g_G + gi + 2));
    long long ti = r * HH + j;
    float2 tv0 = __half22float2(*(const __half2*)(g_T + ti));
    float2 tv1 = __half22float2(*(const __half2*)(g_T + ti + 2));
    float4 wv = *(const float4*)(g_wlast + j);
    float4 bv = *(const float4*)(gate_b + j);
    float4 fv = *(const float4*)(feat + r * HH + j);

    float zx = gv0.x + tv0.x + e * wv.x + bv.x;
    float zy = gv0.y + tv0.y + e * wv.y + bv.y;
    float zz = gv1.x + tv1.x + e * wv.z + bv.z;
    float zw = gv1.y + tv1.y + e * wv.w + bv.w;
    float4 o;
    o.x = fv.x / (1.0f + expf(-zx));
    o.y = fv.y / (1.0f + expf(-zy));
    o.z = fv.z / (1.0f + expf(-zz));
    o.w = fv.w / (1.0f + expf(-zw));
    split4_store(o, g_h0h, g_h0l, r * H3 + m * HH + j);
}

// ----------------------------------------------------------------------------
// Degree (float4 vectorized: 256 threads x 4 = 1024 cols) + normalized adjacency
// ----------------------------------------------------------------------------
__global__ void degree_kernel(const float* __restrict__ sp, const float* __restrict__ tp) {
    __shared__ float sh[8];
    long long b = blockIdx.y, i = blockIdx.x;
    const float4* rs = (const float4*)(sp + (b * SS + i) * SS);
    const float4* rt = (const float4*)(tp + (b * SS + i) * SS);
    float4 a = rs[threadIdx.x], c = rt[threadIdx.x];
    float s = a.x + a.y + a.z + a.w + c.x + c.y + c.z + c.w;
    #pragma unroll
    for (int o = 16; o; o >>= 1) s += __shfl_down_sync(0xffffffffu, s, o);
    int lane = threadIdx.x & 31, w = threadIdx.x >> 5;
    if (lane == 0) sh[w] = s;
    __syncthreads();
    if (threadIdx.x == 0) {
        float D = 1.0f + 0.5f * (sh[0] + sh[1] + sh[2] + sh[3] + sh[4] + sh[5] + sh[6] + sh[7]);
        g_dsi[b * SS + i] = 1.0f / sqrtf(D + EPSV);
    }
}

__global__ void normadj_kernel(const float* __restrict__ sp, const float* __restrict__ tp) {
    long long n4 = (long long)BB * SS * SS / 4;
    for (long long g = (long long)blockIdx.x * blockDim.x + threadIdx.x; g < n4;
         g += (long long)gridDim.x * blockDim.x) {
        long long e = g * 4;
        int b = (int)(e / ((long long)SS * SS));
        long long rrem = e % ((long long)SS * SS);
        int i = (int)(rrem / SS);
        int j = (int)(rrem % SS);
        float4 a = *(const float4*)(sp + e);
        float4 c = *(const float4*)(tp + e);
        float di = g_dsi[(long long)b * SS + i];
        const float* dj = g_dsi + (long long)b * SS + j;
        float4 o;
        o.x = (0.5f * (a.x + c.x) + (j + 0 == i ? 1.0f : 0.0f)) * di * dj[0];
        o.y = (0.5f * (a.y + c.y) + (j + 1 == i ? 1.0f : 0.0f)) * di * dj[1];
        o.z = (0.5f * (a.z + c.z) + (j + 2 == i ? 1.0f : 0.0f)) * di * dj[2];
        o.w = (0.5f * (a.w + c.w) + (j + 3 == i ? 1.0f : 0.0f)) * di * dj[3];
        store4h(o, g_adj, e);
    }
}

// ----------------------------------------------------------------------------
// Classifier
// ----------------------------------------------------------------------------
__global__ void classifier_kernel(const float* __restrict__ bc, float* __restrict__ out) {
    __shared__ float sh[HH];
    long long r = blockIdx.x;
    for (int k = threadIdx.x; k < HH; k += 224)
        sh[k] = __half2float(g_hh[r * HH + k]) + __half2float(g_hl[r * HH + k]);
    __syncthreads();
    int w = threadIdx.x >> 5, lane = threadIdx.x & 31;
    if (w < CC) {
        const float* wrow = g_WcT + w * HH;
        float s = 0.0f;
        #pragma unroll
        for (int k = lane; k < HH; k += 32) s += sh[k] * wrow[k];
        #pragma unroll
        for (int o = 16; o; o >>= 1) s += __shfl_down_sync(0xffffffffu, s, o);
        if (lane == 0) out[r * CC + w] = s + bc[w];
    }
}

// ----------------------------------------------------------------------------
// Launch (launch #5 = batched gating GEMM, for ncu -s 5 -c 1)
// ----------------------------------------------------------------------------
extern "C" void kernel_launch(void* const* d_in, const int* in_sizes, int n_in,
                              void* d_out, int out_size) {
    const float* text   = (const float*)d_in[0];
    const float* audio  = (const float*)d_in[1];
    const float* visual = (const float*)d_in[2];
    const float* sp     = (const float*)d_in[3];
    const float* tp     = (const float*)d_in[4];
    const float* gate_W = (const float*)d_in[6];
    const float* gate_b = (const float*)d_in[7];
    const float* W0 = (const float*)d_in[8];
    const float* b0 = (const float*)d_in[9];
    const float* W1 = (const float*)d_in[10];
    const float* b1 = (const float*)d_in[11];
    const float* W2 = (const float*)d_in[12];
    const float* b2 = (const float*)d_in[13];
    const float* Wc = (const float*)d_in[14];
    const float* bc = (const float*)d_in[15];
    float* out = (float*)d_out;

    static bool attr_done = false;
    if (!attr_done) {
        cudaFuncSetAttribute(mma_gemm<0, 1, 0>, cudaFuncAttributeMaxDynamicSharedMemorySize, SMEM_BYTES);
        cudaFuncSetAttribute(mma_gemm<0, 0, 0>, cudaFuncAttributeMaxDynamicSharedMemorySize, SMEM_BYTES);
        cudaFuncSetAttribute(mma_gemm<1, 1, 1>, cudaFuncAttributeMaxDynamicSharedMemorySize, SMEM_BYTES);
        attr_done = true;
    }

    #define SYM(p, s) cudaGetSymbolAddress((void**)&p, s)
    __half *f, *tot, *G, *T, *h0h, *h0l;
    __half *adj, *tmp, *hh, *hl;
    __half *Aw, *Wh, *W0p, *W1p, *W2p;
    SYM(f, g_f); SYM(tot, g_tot);
    SYM(G, g_G); SYM(T, g_T);
    SYM(h0h, g_h0h); SYM(h0l, g_h0l);
    SYM(adj, g_adj);
    SYM(tmp, g_tmp); SYM(hh, g_hh); SYM(hl, g_hl);
    SYM(Aw, g_Aw); SYM(Wh, g_Wh);
    SYM(W0p, g_W0); SYM(W1p, g_W1); SYM(W2p, g_W2);
    #undef SYM

    long long sF = (long long)MM * HH;
    dim3 gemm_grid(HH / BN, MM / BM, 1);
    dim3 gate_grid(HH / BN, MM / BM, 3);
    dim3 adj_grid(HH / BN, SS / BM, BB);
    long long sAdj = (long long)SS * SS, sL = (long long)SS * HH;

    // launches 0-4: prep needed by the gating GEMM
    prep_weights<<<(HH * HH + 255) / 256, 256>>>(gate_W);                    // 0
    transpose_wc<<<(HH * CC + 255) / 256, 256>>>(Wc);                        // 1
    prep_feats<<<MM, 128>>>(text, audio, visual);                            // 2
    degree_kernel<<<dim3(SS, BB), 256>>>(sp, tp);                            // 3
    normadj_kernel<<<8192, 256>>>(sp, tp);                                   // 4

    // launch 5: batched gating GEMM (1 MMA: feat single x weight single)
    mma_gemm<0, 1, 0><<<gate_grid, 256, SMEM_BYTES>>>(f, nullptr, Aw, nullptr,
                                                      G, nullptr, MM, HH, HH, sF, 0, sF);
    mma_gemm<0, 1, 0><<<gemm_grid, 256, SMEM_BYTES>>>(tot, nullptr, Wh, nullptr,
                                                      T, nullptr, MM, HH, HH, 0, 0, 0);
    gate_fuse_kernel<<<dim3(MM, 3), 128>>>(gate_b, text, audio, visual);

    // weight conversions for the GNN
    conv_w<<<(H3 * HH / 4 + 255) / 256, 256>>>(W0, W0p, H3 * HH / 4);
    conv_w<<<(HH * HH / 4 + 255) / 256, 256>>>(W1, W1p, HH * HH / 4);
    conv_w<<<(HH * HH / 4 + 255) / 256, 256>>>(W2, W2p, HH * HH / 4);

    // spectral GNN: feature GEMMs 2-MMA (hi/lo A), adj GEMMs 1-MMA
    mma_gemm<0, 0, 0><<<gemm_grid, 256, SMEM_BYTES>>>(h0h, h0l, W0p, nullptr,
                                                      tmp, nullptr, MM, HH, H3, 0, 0, 0);
    mma_gemm<1, 1, 1><<<adj_grid, 256, SMEM_BYTES>>>(adj, nullptr, tmp, b0,
                                                     hh, hl, SS, HH, SS, sAdj, sL, sL);

    mma_gemm<0, 0, 0><<<gemm_grid, 256, SMEM_BYTES>>>(hh, hl, W1p, nullptr,
                                                      tmp, nullptr, MM, HH, HH, 0, 0, 0);
    mma_gemm<1, 1, 1><<<adj_grid, 256, SMEM_BYTES>>>(adj, nullptr, tmp, b1,
                                                     hh, hl, SS, HH, SS, sAdj, sL, sL);

    mma_gemm<0, 0, 0><<<gemm_grid, 256, SMEM_BYTES>>>(hh, hl, W2p, nullptr,
                                                      tmp, nullptr, MM, HH, HH, 0, 0, 0);
    mma_gemm<1, 1, 1><<<adj_grid, 256, SMEM_BYTES>>>(adj, nullptr, tmp, b2,
                                                     hh, hl, SS, HH, SS, sAdj, sL, sL);

    // classifier
    classifier_kernel<<<MM, 224>>>(bc, out);
}

// round 10
// speedup vs baseline: 2.3278x; 1.2727x over previous
#include <cuda_runtime.h>
#include <cuda_fp16.h>
#include <cstdint>
#include <math.h>

// Problem dims (fixed by the dataset)
#define BB 16
#define SS 1024
#define HH 512
#define CC 7
#define MM (BB * SS)        // 16384 rows
#define H3 (3 * HH)         // 1536
#define EPSV 1e-10f

// GEMM tiling
#define BM 128
#define BN 128
#define BK 32
#define LDA 40              // halves, padded (80B rows: cp.async-aligned, ldmatrix conflict-free)
#define LDB 136             // halves, padded (272B rows)
#define NSTG 3
#define STAGE_H (BM * LDA + BK * LDB)              // halves per stage = 9472
#define SMEM_BYTES (NSTG * STAGE_H * 2)            // 56832 B

// ----------------------------------------------------------------------------
// Static scratch (single fp16 planes everywhere; no allocations anywhere)
// ----------------------------------------------------------------------------
__device__ __half g_f[3 * MM * HH];                         // text/audio/visual
__device__ __half g_tot[MM * HH];
__device__ __half g_G[3 * MM * HH];                         // gating GEMM out
__device__ __half g_T[MM * HH];
__device__ __half g_h0[MM * H3];                            // gated features
__device__ __half g_adj[BB * SS * SS];
__device__ __half g_tmp[MM * HH];                           // feature GEMM out
__device__ __half g_h[MM * HH];                             // layer activations
__device__ __half g_Aw[HH * HH];
__device__ __half g_Wh[HH * HH];
__device__ __half g_W0[H3 * HH];
__device__ __half g_W1[HH * HH];
__device__ __half g_W2[HH * HH];
__device__ float g_ent[3 * MM];
__device__ float g_dsi[BB * SS];
__device__ float g_wlast[HH];
__device__ float g_WcT[CC * HH];

// ----------------------------------------------------------------------------
// Helpers
// ----------------------------------------------------------------------------
__device__ __forceinline__ unsigned s2u(const void* p) {
    return (unsigned)__cvta_generic_to_shared(p);
}

__device__ __forceinline__ void store4h(float4 v, __half* p, long long idx) {
    *(__half2*)(p + idx)     = __halves2half2(__float2half_rn(v.x), __float2half_rn(v.y));
    *(__half2*)(p + idx + 2) = __halves2half2(__float2half_rn(v.z), __float2half_rn(v.w));
}

#define MMA16816(d, a, b)                                                  \
    asm volatile(                                                          \
        "mma.sync.aligned.m16n8k16.row.col.f32.f16.f16.f32 "               \
        "{%0,%1,%2,%3}, {%4,%5,%6,%7}, {%8,%9}, {%0,%1,%2,%3};\n"          \
        : "+f"(d[0]), "+f"(d[1]), "+f"(d[2]), "+f"(d[3])                   \
        : "r"(a[0]), "r"(a[1]), "r"(a[2]), "r"(a[3]), "r"(b[0]), "r"(b[1]))

#define LDSM_X4(r0, r1, r2, r3, addr)                                      \
    asm volatile("ldmatrix.sync.aligned.m8n8.x4.shared.b16 "               \
                 "{%0,%1,%2,%3}, [%4];\n"                                  \
                 : "=r"(r0), "=r"(r1), "=r"(r2), "=r"(r3) : "r"(addr))

#define LDSM_X4T(r0, r1, r2, r3, addr)                                     \
    asm volatile("ldmatrix.sync.aligned.m8n8.x4.trans.shared.b16 "         \
                 "{%0,%1,%2,%3}, [%4];\n"                                  \
                 : "=r"(r0), "=r"(r1), "=r"(r2), "=r"(r3) : "r"(addr))

#define CP16(dst, src)                                                     \
    asm volatile("cp.async.cg.shared.global [%0], [%1], 16;\n"             \
                 :: "r"(dst), "l"(src))
#define CP_COMMIT asm volatile("cp.async.commit_group;\n" ::: "memory")
#define CP_WAIT(n) asm volatile("cp.async.wait_group %0;\n" :: "n"(n) : "memory")

// ----------------------------------------------------------------------------
// fp16 tensor-core GEMM, 3-stage cp.async pipeline, 1 MMA per logical tile.
// C = A[M,K] @ B[K,N].  EPI: 0 = none, 1 = bias+relu.
// ----------------------------------------------------------------------------
template <int EPI>
__global__ void __launch_bounds__(256, 2) mma_gemm(
    const __half* __restrict__ A0g, const __half* __restrict__ B0g,
    const float* __restrict__ bias, __half* __restrict__ Chg,
    int M, int N, int K, long long sA, long long sB, long long sC)
{
    extern __shared__ __half sm[];
    // stage layout (halves): A0[0,5120) B0[5120,9472)

    const __half* A0 = A0g + (long long)blockIdx.z * sA;
    const __half* B0 = B0g + (long long)blockIdx.z * sB;
    __half* Ch = Chg + (long long)blockIdx.z * sC;

    int t = threadIdx.x, lane = t & 31, wid = t >> 5;
    int warp_m = wid >> 2, warp_n = wid & 3;    // 2 x 4 warps
    int brow = blockIdx.y * BM, bcol = blockIdx.x * BN;
    int KT = K / BK;

    float acc[4][4][4];
    #pragma unroll
    for (int i = 0; i < 4; i++)
        #pragma unroll
        for (int j = 0; j < 4; j++)
            #pragma unroll
            for (int q = 0; q < 4; q++) acc[i][j][q] = 0.0f;

    auto load_tile = [&](int kt, int s) {
        int k0 = kt * BK;
        __half* st = sm + s * STAGE_H;
        #pragma unroll
        for (int i = 0; i < 2; i++) {
            int q = t + i * 256;
            int ra = q >> 2, ca = (q & 3) << 3;         // A: 128 rows x 4 chunks
            long long asrc = (long long)(brow + ra) * K + k0 + ca;
            CP16(s2u(st + ra * LDA + ca), A0 + asrc);
            int rb = q >> 4, cb = (q & 15) << 3;        // B: 32 rows x 16 chunks
            long long bsrc = (long long)(k0 + rb) * N + bcol + cb;
            CP16(s2u(st + BM * LDA + rb * LDB + cb), B0 + bsrc);
        }
    };

    load_tile(0, 0); CP_COMMIT;
    load_tile(1, 1); CP_COMMIT;

    int s = 0;
    for (int kt = 0; kt < KT; kt++) {
        if (kt + 2 < KT) { CP_WAIT(1); } else { CP_WAIT(0); }
        __syncthreads();

        if (kt + 2 < KT) { load_tile(kt + 2, (s + 2) % NSTG); CP_COMMIT; }

        const __half* cA0 = sm + s * STAGE_H;
        const __half* cB0 = cA0 + BM * LDA;

        #pragma unroll
        for (int kk = 0; kk < BK; kk += 16) {
            unsigned a0[4][4], b0[4][2];
            int arow = warp_m * 64 + (lane & 15);
            int acol = kk + ((lane >> 4) << 3);
            #pragma unroll
            for (int tm = 0; tm < 4; tm++)
                LDSM_X4(a0[tm][0], a0[tm][1], a0[tm][2], a0[tm][3],
                        s2u(&cA0[(arow + tm * 16) * LDA + acol]));
            int brow_ = kk + (lane & 15);
            #pragma unroll
            for (int tp = 0; tp < 2; tp++) {
                int bc = warp_n * 32 + tp * 16 + ((lane >> 4) << 3);
                LDSM_X4T(b0[2 * tp][0], b0[2 * tp][1],
                         b0[2 * tp + 1][0], b0[2 * tp + 1][1],
                         s2u(&cB0[brow_ * LDB + bc]));
            }
            #pragma unroll
            for (int tm = 0; tm < 4; tm++)
                #pragma unroll
                for (int tn = 0; tn < 4; tn++)
                    MMA16816(acc[tm][tn], a0[tm], b0[tn]);
        }
        s = (s + 1) % NSTG;
    }

    // ---- epilogue ----
    int g = lane >> 2, tig = lane & 3;
    #pragma unroll
    for (int tm = 0; tm < 4; tm++)
        #pragma unroll
        for (int tn = 0; tn < 4; tn++) {
            int row = brow + warp_m * 64 + tm * 16 + g;
            int col = bcol + warp_n * 32 + tn * 8 + tig * 2;
            float2 v0 = make_float2(acc[tm][tn][0], acc[tm][tn][1]);
            float2 v1 = make_float2(acc[tm][tn][2], acc[tm][tn][3]);
            if (EPI == 1) {
                float b0v = bias[col], b1v = bias[col + 1];
                v0.x = fmaxf(v0.x + b0v, 0.0f); v0.y = fmaxf(v0.y + b1v, 0.0f);
                v1.x = fmaxf(v1.x + b0v, 0.0f); v1.y = fmaxf(v1.y + b1v, 0.0f);
            }
            long long idx0 = (long long)row * N + col;
            long long idx1 = (long long)(row + 8) * N + col;
            *(__half2*)(Ch + idx0) = __halves2half2(__float2half_rn(v0.x), __float2half_rn(v0.y));
            *(__half2*)(Ch + idx1) = __halves2half2(__float2half_rn(v1.x), __float2half_rn(v1.y));
        }
}

// ----------------------------------------------------------------------------
// Fused: entropy + fp16 convert of feats + total
// ----------------------------------------------------------------------------
__global__ void prep_feats(const float* __restrict__ text,
                           const float* __restrict__ audio,
                           const float* __restrict__ visual) {
    __shared__ float sh[3][4];
    long long r = blockIdx.x;
    int tid = threadIdx.x, lane = tid & 31, w = tid >> 5;
    long long off = r * HH + tid * 4;
    float4 v0 = *(const float4*)(text + off);
    float4 v1 = *(const float4*)(audio + off);
    float4 v2 = *(const float4*)(visual + off);

    float a0x = fabsf(v0.x), a0y = fabsf(v0.y), a0z = fabsf(v0.z), a0w = fabsf(v0.w);
    float a1x = fabsf(v1.x), a1y = fabsf(v1.y), a1z = fabsf(v1.z), a1w = fabsf(v1.w);
    float a2x = fabsf(v2.x), a2y = fabsf(v2.y), a2z = fabsf(v2.z), a2w = fabsf(v2.w);
    float s0 = a0x + a0y + a0z + a0w;
    float s1 = a1x + a1y + a1z + a1w;
    float s2 = a2x + a2y + a2z + a2w;
    #pragma unroll
    for (int o = 16; o; o >>= 1) {
        s0 += __shfl_down_sync(0xffffffffu, s0, o);
        s1 += __shfl_down_sync(0xffffffffu, s1, o);
        s2 += __shfl_down_sync(0xffffffffu, s2, o);
    }
    if (lane == 0) { sh[0][w] = s0; sh[1][w] = s1; sh[2][w] = s2; }
    __syncthreads();
    float t0 = sh[0][0] + sh[0][1] + sh[0][2] + sh[0][3];
    float t1 = sh[1][0] + sh[1][1] + sh[1][2] + sh[1][3];
    float t2 = sh[2][0] + sh[2][1] + sh[2][2] + sh[2][3];
    float i0 = 1.0f / (t0 + EPSV), i1 = 1.0f / (t1 + EPSV), i2 = 1.0f / (t2 + EPSV);

    float e0, e1, e2;
    {
        float f0 = a0x * i0, f1 = a0y * i0, f2 = a0z * i0, f3 = a0w * i0;
        e0 = f0 * logf(f0 + EPSV) + f1 * logf(f1 + EPSV)
           + f2 * logf(f2 + EPSV) + f3 * logf(f3 + EPSV);
    }
    {
        float f0 = a1x * i1, f1 = a1y * i1, f2 = a1z * i1, f3 = a1w * i1;
        e1 = f0 * logf(f0 + EPSV) + f1 * logf(f1 + EPSV)
           + f2 * logf(f2 + EPSV) + f3 * logf(f3 + EPSV);
    }
    {
        float f0 = a2x * i2, f1 = a2y * i2, f2 = a2z * i2, f3 = a2w * i2;
        e2 = f0 * logf(f0 + EPSV) + f1 * logf(f1 + EPSV)
           + f2 * logf(f2 + EPSV) + f3 * logf(f3 + EPSV);
    }
    #pragma unroll
    for (int o = 16; o; o >>= 1) {
        e0 += __shfl_down_sync(0xffffffffu, e0, o);
        e1 += __shfl_down_sync(0xffffffffu, e1, o);
        e2 += __shfl_down_sync(0xffffffffu, e2, o);
    }
    __syncthreads();
    if (lane == 0) { sh[0][w] = e0; sh[1][w] = e1; sh[2][w] = e2; }
    __syncthreads();
    if (tid == 0) {
        g_ent[0 * MM + r] = -(sh[0][0] + sh[0][1] + sh[0][2] + sh[0][3]);
        g_ent[1 * MM + r] = -(sh[1][0] + sh[1][1] + sh[1][2] + sh[1][3]);
        g_ent[2 * MM + r] = -(sh[2][0] + sh[2][1] + sh[2][2] + sh[2][3]);
    }

    store4h(v0, g_f, 0LL * MM * HH + off);
    store4h(v1, g_f, 1LL * MM * HH + off);
    store4h(v2, g_f, 2LL * MM * HH + off);
    float4 tq = make_float4(v0.x + v1.x + v2.x, v0.y + v1.y + v2.y,
                            v0.z + v1.z + v2.z, v0.w + v1.w + v2.w);
    store4h(tq, g_tot, off);
}

// ----------------------------------------------------------------------------
// Weight prep (single fp16 planes)
// ----------------------------------------------------------------------------
__global__ void prep_weights(const float* __restrict__ gW) {
    int idx = blockIdx.x * blockDim.x + threadIdx.x;
    if (idx < HH * HH) {
        float wa = gW[idx];
        float wb = gW[HH * HH + idx];
        float wc = gW[2 * HH * HH + idx];
        g_Aw[idx] = __float2half_rn(wa + wb - 0.5f * wc);
        g_Wh[idx] = __float2half_rn(0.5f * wc);
    }
    if (idx < HH) g_wlast[idx] = gW[3 * HH * HH + idx];
}

__global__ void conv_w(const float* __restrict__ src, __half* __restrict__ dst, int n4) {
    int i = blockIdx.x * blockDim.x + threadIdx.x;
    if (i < n4) {
        float4 v = ((const float4*)src)[i];
        store4h(v, dst, (long long)i * 4);
    }
}

__global__ void transpose_wc(const float* __restrict__ Wc) {
    int idx = blockIdx.x * blockDim.x + threadIdx.x;
    if (idx < HH * CC) {
        int k = idx / CC, c = idx % CC;
        g_WcT[c * HH + k] = Wc[k * CC + c];
    }
}

// ----------------------------------------------------------------------------
// gate_fuse: h0 = sigmoid(G + T + ent*wlast + gate_b) * feat   (single plane)
// ----------------------------------------------------------------------------
__global__ void gate_fuse_kernel(const float* __restrict__ gate_b,
                                 const float* __restrict__ text,
                                 const float* __restrict__ audio,
                                 const float* __restrict__ visual) {
    long long r = blockIdx.x;
    int m = blockIdx.y;
    const float* feat = (m == 0) ? text : (m == 1) ? audio : visual;
    float e = g_ent[(long long)m * MM + r];
    int j = threadIdx.x * 4;
    long long gi = ((long long)m * MM + r) * HH + j;
    float2 gv0 = __half22float2(*(const __half2*)(g_G + gi));
    float2 gv1 = __half22float2(*(const __half2*)(g_G + gi + 2));
    long long ti = r * HH + j;
    float2 tv0 = __half22float2(*(const __half2*)(g_T + ti));
    float2 tv1 = __half22float2(*(const __half2*)(g_T + ti + 2));
    float4 wv = *(const float4*)(g_wlast + j);
    float4 bv = *(const float4*)(gate_b + j);
    float4 fv = *(const float4*)(feat + r * HH + j);

    float zx = gv0.x + tv0.x + e * wv.x + bv.x;
    float zy = gv0.y + tv0.y + e * wv.y + bv.y;
    float zz = gv1.x + tv1.x + e * wv.z + bv.z;
    float zw = gv1.y + tv1.y + e * wv.w + bv.w;
    float4 o;
    o.x = fv.x / (1.0f + expf(-zx));
    o.y = fv.y / (1.0f + expf(-zy));
    o.z = fv.z / (1.0f + expf(-zz));
    o.w = fv.w / (1.0f + expf(-zw));
    store4h(o, g_h0, r * H3 + m * HH + j);
}

// ----------------------------------------------------------------------------
// Degree (float4 vectorized) + normalized adjacency (single fp16)
// ----------------------------------------------------------------------------
__global__ void degree_kernel(const float* __restrict__ sp, const float* __restrict__ tp) {
    __shared__ float sh[8];
    long long b = blockIdx.y, i = blockIdx.x;
    const float4* rs = (const float4*)(sp + (b * SS + i) * SS);
    const float4* rt = (const float4*)(tp + (b * SS + i) * SS);
    float4 a = rs[threadIdx.x], c = rt[threadIdx.x];
    float s = a.x + a.y + a.z + a.w + c.x + c.y + c.z + c.w;
    #pragma unroll
    for (int o = 16; o; o >>= 1) s += __shfl_down_sync(0xffffffffu, s, o);
    int lane = threadIdx.x & 31, w = threadIdx.x >> 5;
    if (lane == 0) sh[w] = s;
    __syncthreads();
    if (threadIdx.x == 0) {
        float D = 1.0f + 0.5f * (sh[0] + sh[1] + sh[2] + sh[3] + sh[4] + sh[5] + sh[6] + sh[7]);
        g_dsi[b * SS + i] = 1.0f / sqrtf(D + EPSV);
    }
}

__global__ void normadj_kernel(const float* __restrict__ sp, const float* __restrict__ tp) {
    long long n4 = (long long)BB * SS * SS / 4;
    for (long long g = (long long)blockIdx.x * blockDim.x + threadIdx.x; g < n4;
         g += (long long)gridDim.x * blockDim.x) {
        long long e = g * 4;
        int b = (int)(e / ((long long)SS * SS));
        long long rrem = e % ((long long)SS * SS);
        int i = (int)(rrem / SS);
        int j = (int)(rrem % SS);
        float4 a = *(const float4*)(sp + e);
        float4 c = *(const float4*)(tp + e);
        float di = g_dsi[(long long)b * SS + i];
        const float* dj = g_dsi + (long long)b * SS + j;
        float4 o;
        o.x = (0.5f * (a.x + c.x) + (j + 0 == i ? 1.0f : 0.0f)) * di * dj[0];
        o.y = (0.5f * (a.y + c.y) + (j + 1 == i ? 1.0f : 0.0f)) * di * dj[1];
        o.z = (0.5f * (a.z + c.z) + (j + 2 == i ? 1.0f : 0.0f)) * di * dj[2];
        o.w = (0.5f * (a.w + c.w) + (j + 3 == i ? 1.0f : 0.0f)) * di * dj[3];
        store4h(o, g_adj, e);
    }
}

// ----------------------------------------------------------------------------
// Classifier
// ----------------------------------------------------------------------------
__global__ void classifier_kernel(const float* __restrict__ bc, float* __restrict__ out) {
    __shared__ float sh[HH];
    long long r = blockIdx.x;
    for (int k = threadIdx.x; k < HH; k += 224)
        sh[k] = __half2float(g_h[r * HH + k]);
    __syncthreads();
    int w = threadIdx.x >> 5, lane = threadIdx.x & 31;
    if (w < CC) {
        const float* wrow = g_WcT + w * HH;
        float s = 0.0f;
        #pragma unroll
        for (int k = lane; k < HH; k += 32) s += sh[k] * wrow[k];
        #pragma unroll
        for (int o = 16; o; o >>= 1) s += __shfl_down_sync(0xffffffffu, s, o);
        if (lane == 0) out[r * CC + w] = s + bc[w];
    }
}

// ----------------------------------------------------------------------------
// Launch (launch #5 = batched gating GEMM, for ncu -s 5 -c 1)
// ----------------------------------------------------------------------------
extern "C" void kernel_launch(void* const* d_in, const int* in_sizes, int n_in,
                              void* d_out, int out_size) {
    const float* text   = (const float*)d_in[0];
    const float* audio  = (const float*)d_in[1];
    const float* visual = (const float*)d_in[2];
    const float* sp     = (const float*)d_in[3];
    const float* tp     = (const float*)d_in[4];
    const float* gate_W = (const float*)d_in[6];
    const float* gate_b = (const float*)d_in[7];
    const float* W0 = (const float*)d_in[8];
    const float* b0 = (const float*)d_in[9];
    const float* W1 = (const float*)d_in[10];
    const float* b1 = (const float*)d_in[11];
    const float* W2 = (const float*)d_in[12];
    const float* b2 = (const float*)d_in[13];
    const float* Wc = (const float*)d_in[14];
    const float* bc = (const float*)d_in[15];
    float* out = (float*)d_out;

    static bool attr_done = false;
    if (!attr_done) {
        cudaFuncSetAttribute(mma_gemm<0>, cudaFuncAttributeMaxDynamicSharedMemorySize, SMEM_BYTES);
        cudaFuncSetAttribute(mma_gemm<1>, cudaFuncAttributeMaxDynamicSharedMemorySize, SMEM_BYTES);
        attr_done = true;
    }

    #define SYM(p, s) cudaGetSymbolAddress((void**)&p, s)
    __half *f, *tot, *G, *T, *h0, *adj, *tmp, *h;
    __half *Aw, *Wh, *W0p, *W1p, *W2p;
    SYM(f, g_f); SYM(tot, g_tot);
    SYM(G, g_G); SYM(T, g_T);
    SYM(h0, g_h0); SYM(adj, g_adj);
    SYM(tmp, g_tmp); SYM(h, g_h);
    SYM(Aw, g_Aw); SYM(Wh, g_Wh);
    SYM(W0p, g_W0); SYM(W1p, g_W1); SYM(W2p, g_W2);
    #undef SYM

    long long sF = (long long)MM * HH;
    dim3 gemm_grid(HH / BN, MM / BM, 1);
    dim3 gate_grid(HH / BN, MM / BM, 3);
    dim3 adj_grid(HH / BN, SS / BM, BB);
    long long sAdj = (long long)SS * SS, sL = (long long)SS * HH;

    // launches 0-4: prep
    prep_weights<<<(HH * HH + 255) / 256, 256>>>(gate_W);                    // 0
    transpose_wc<<<(HH * CC + 255) / 256, 256>>>(Wc);                        // 1
    prep_feats<<<MM, 128>>>(text, audio, visual);                            // 2
    degree_kernel<<<dim3(SS, BB), 256>>>(sp, tp);                            // 3
    normadj_kernel<<<8192, 256>>>(sp, tp);                                   // 4

    // launch 5: batched gating GEMM
    mma_gemm<0><<<gate_grid, 256, SMEM_BYTES>>>(f, Aw, nullptr, G,
                                                MM, HH, HH, sF, 0, sF);
    mma_gemm<0><<<gemm_grid, 256, SMEM_BYTES>>>(tot, Wh, nullptr, T,
                                                MM, HH, HH, 0, 0, 0);
    gate_fuse_kernel<<<dim3(MM, 3), 128>>>(gate_b, text, audio, visual);

    // weight conversions for the GNN
    conv_w<<<(H3 * HH / 4 + 255) / 256, 256>>>(W0, W0p, H3 * HH / 4);
    conv_w<<<(HH * HH / 4 + 255) / 256, 256>>>(W1, W1p, HH * HH / 4);
    conv_w<<<(HH * HH / 4 + 255) / 256, 256>>>(W2, W2p, HH * HH / 4);

    // spectral GNN (all GEMMs 1 MMA)
    mma_gemm<0><<<gemm_grid, 256, SMEM_BYTES>>>(h0, W0p, nullptr, tmp,
                                                MM, HH, H3, 0, 0, 0);
    mma_gemm<1><<<adj_grid, 256, SMEM_BYTES>>>(adj, tmp, b0, h,
                                               SS, HH, SS, sAdj, sL, sL);

    mma_gemm<0><<<gemm_grid, 256, SMEM_BYTES>>>(h, W1p, nullptr, tmp,
                                                MM, HH, HH, 0, 0, 0);
    mma_gemm<1><<<adj_grid, 256, SMEM_BYTES>>>(adj, tmp, b1, h,
                                               SS, HH, SS, sAdj, sL, sL);

    mma_gemm<0><<<gemm_grid, 256, SMEM_BYTES>>>(h, W2p, nullptr, tmp,
                                                MM, HH, HH, 0, 0, 0);
    mma_gemm<1><<<adj_grid, 256, SMEM_BYTES>>>(adj, tmp, b2, h,
                                               SS, HH, SS, sAdj, sL, sL);

    // classifier
    classifier_kernel<<<MM, 224>>>(bc, out);
}

// round 11
// speedup vs baseline: 2.4337x; 1.0455x over previous
#include <cuda_runtime.h>
#include <cuda_fp16.h>
#include <cstdint>
#include <math.h>

// Problem dims (fixed by the dataset)
#define BB 16
#define SS 1024
#define HH 512
#define CC 7
#define MM (BB * SS)        // 16384 rows
#define H3 (3 * HH)         // 1536
#define EPSV 1e-10f

// GEMM tiling
#define BM 128
#define BN 128
#define BK 32
#define LDA 40              // halves, padded (80B rows: cp.async-aligned, ldmatrix conflict-free)
#define LDB 136             // halves, padded (272B rows)
#define NSTG 3
#define STAGE_H (BM * LDA + BK * LDB)              // halves per stage = 9472
#define SMEM_BYTES (NSTG * STAGE_H * 2)            // 56832 B

// ----------------------------------------------------------------------------
// Static scratch (single fp16 planes; no allocations anywhere)
// ----------------------------------------------------------------------------
__device__ __half g_f[4 * MM * HH];                         // text/audio/visual/total
__device__ __half g_G[4 * MM * HH];                         // gating GEMM out (slot 3 = T)
__device__ __half g_h0[MM * H3];                            // gated features
__device__ __half g_sumh[BB * SS * SS];                     // fp16(sp+tp)
__device__ __half g_adj[BB * SS * SS];
__device__ __half g_tmp[MM * HH];                           // feature GEMM out
__device__ __half g_h[MM * HH];                             // layer activations
__device__ __half g_Aw[HH * HH];
__device__ __half g_Wh[HH * HH];
__device__ __half g_W0[H3 * HH];
__device__ __half g_W1[HH * HH];
__device__ __half g_W2[HH * HH];
__device__ float g_ent[3 * MM];
__device__ float g_dsi[BB * SS];
__device__ float g_wlast[HH];
__device__ float g_WcT[CC * HH];

// ----------------------------------------------------------------------------
// Helpers
// ----------------------------------------------------------------------------
__device__ __forceinline__ unsigned s2u(const void* p) {
    return (unsigned)__cvta_generic_to_shared(p);
}

__device__ __forceinline__ void store4h(float4 v, __half* p, long long idx) {
    *(__half2*)(p + idx)     = __halves2half2(__float2half_rn(v.x), __float2half_rn(v.y));
    *(__half2*)(p + idx + 2) = __halves2half2(__float2half_rn(v.z), __float2half_rn(v.w));
}

#define MMA16816(d, a, b)                                                  \
    asm volatile(                                                          \
        "mma.sync.aligned.m16n8k16.row.col.f32.f16.f16.f32 "               \
        "{%0,%1,%2,%3}, {%4,%5,%6,%7}, {%8,%9}, {%0,%1,%2,%3};\n"          \
        : "+f"(d[0]), "+f"(d[1]), "+f"(d[2]), "+f"(d[3])                   \
        : "r"(a[0]), "r"(a[1]), "r"(a[2]), "r"(a[3]), "r"(b[0]), "r"(b[1]))

#define LDSM_X4(r0, r1, r2, r3, addr)                                      \
    asm volatile("ldmatrix.sync.aligned.m8n8.x4.shared.b16 "               \
                 "{%0,%1,%2,%3}, [%4];\n"                                  \
                 : "=r"(r0), "=r"(r1), "=r"(r2), "=r"(r3) : "r"(addr))

#define LDSM_X4T(r0, r1, r2, r3, addr)                                     \
    asm volatile("ldmatrix.sync.aligned.m8n8.x4.trans.shared.b16 "         \
                 "{%0,%1,%2,%3}, [%4];\n"                                  \
                 : "=r"(r0), "=r"(r1), "=r"(r2), "=r"(r3) : "r"(addr))

#define CP16(dst, src)                                                     \
    asm volatile("cp.async.cg.shared.global [%0], [%1], 16;\n"             \
                 :: "r"(dst), "l"(src))
#define CP_COMMIT asm volatile("cp.async.commit_group;\n" ::: "memory")
#define CP_WAIT(n) asm volatile("cp.async.wait_group %0;\n" :: "n"(n) : "memory")

// ----------------------------------------------------------------------------
// fp16 tensor-core GEMM, 3-stage cp.async pipeline, 1 MMA per logical tile.
// C = A[M,K] @ B[K,N].  EPI: 0 = none, 1 = bias+relu.
// SELB: 0 = B0g (+z*sB), 1 = gating mode: B = (z < 3) ? B0g : B1g, sB ignored.
// ----------------------------------------------------------------------------
template <int EPI, int SELB>
__global__ void __launch_bounds__(256, 2) mma_gemm(
    const __half* __restrict__ A0g, const __half* __restrict__ B0g,
    const __half* __restrict__ B1g,
    const float* __restrict__ bias, __half* __restrict__ Chg,
    int M, int N, int K, long long sA, long long sB, long long sC)
{
    extern __shared__ __half sm[];
    // stage layout (halves): A0[0,5120) B0[5120,9472)

    const __half* A0 = A0g + (long long)blockIdx.z * sA;
    const __half* B0 = SELB ? ((blockIdx.z < 3) ? B0g : B1g)
                            : (B0g + (long long)blockIdx.z * sB);
    __half* Ch = Chg + (long long)blockIdx.z * sC;

    int t = threadIdx.x, lane = t & 31, wid = t >> 5;
    int warp_m = wid >> 2, warp_n = wid & 3;    // 2 x 4 warps
    int brow = blockIdx.y * BM, bcol = blockIdx.x * BN;
    int KT = K / BK;

    float acc[4][4][4];
    #pragma unroll
    for (int i = 0; i < 4; i++)
        #pragma unroll
        for (int j = 0; j < 4; j++)
            #pragma unroll
            for (int q = 0; q < 4; q++) acc[i][j][q] = 0.0f;

    auto load_tile = [&](int kt, int s) {
        int k0 = kt * BK;
        __half* st = sm + s * STAGE_H;
        #pragma unroll
        for (int i = 0; i < 2; i++) {
            int q = t + i * 256;
            int ra = q >> 2, ca = (q & 3) << 3;         // A: 128 rows x 4 chunks
            long long asrc = (long long)(brow + ra) * K + k0 + ca;
            CP16(s2u(st + ra * LDA + ca), A0 + asrc);
            int rb = q >> 4, cb = (q & 15) << 3;        // B: 32 rows x 16 chunks
            long long bsrc = (long long)(k0 + rb) * N + bcol + cb;
            CP16(s2u(st + BM * LDA + rb * LDB + cb), B0 + bsrc);
        }
    };

    load_tile(0, 0); CP_COMMIT;
    load_tile(1, 1); CP_COMMIT;

    int s = 0;
    for (int kt = 0; kt < KT; kt++) {
        if (kt + 2 < KT) { CP_WAIT(1); } else { CP_WAIT(0); }
        __syncthreads();

        if (kt + 2 < KT) { load_tile(kt + 2, (s + 2) % NSTG); CP_COMMIT; }

        const __half* cA0 = sm + s * STAGE_H;
        const __half* cB0 = cA0 + BM * LDA;

        #pragma unroll
        for (int kk = 0; kk < BK; kk += 16) {
            unsigned a0[4][4], b0[4][2];
            int arow = warp_m * 64 + (lane & 15);
            int acol = kk + ((lane >> 4) << 3);
            #pragma unroll
            for (int tm = 0; tm < 4; tm++)
                LDSM_X4(a0[tm][0], a0[tm][1], a0[tm][2], a0[tm][3],
                        s2u(&cA0[(arow + tm * 16) * LDA + acol]));
            int brow_ = kk + (lane & 15);
            #pragma unroll
            for (int tp = 0; tp < 2; tp++) {
                int bc = warp_n * 32 + tp * 16 + ((lane >> 4) << 3);
                LDSM_X4T(b0[2 * tp][0], b0[2 * tp][1],
                         b0[2 * tp + 1][0], b0[2 * tp + 1][1],
                         s2u(&cB0[brow_ * LDB + bc]));
            }
            #pragma unroll
            for (int tm = 0; tm < 4; tm++)
                #pragma unroll
                for (int tn = 0; tn < 4; tn++)
                    MMA16816(acc[tm][tn], a0[tm], b0[tn]);
        }
        s = (s + 1) % NSTG;
    }

    // ---- epilogue ----
    int g = lane >> 2, tig = lane & 3;
    #pragma unroll
    for (int tm = 0; tm < 4; tm++)
        #pragma unroll
        for (int tn = 0; tn < 4; tn++) {
            int row = brow + warp_m * 64 + tm * 16 + g;
            int col = bcol + warp_n * 32 + tn * 8 + tig * 2;
            float2 v0 = make_float2(acc[tm][tn][0], acc[tm][tn][1]);
            float2 v1 = make_float2(acc[tm][tn][2], acc[tm][tn][3]);
            if (EPI == 1) {
                float b0v = bias[col], b1v = bias[col + 1];
                v0.x = fmaxf(v0.x + b0v, 0.0f); v0.y = fmaxf(v0.y + b1v, 0.0f);
                v1.x = fmaxf(v1.x + b0v, 0.0f); v1.y = fmaxf(v1.y + b1v, 0.0f);
            }
            long long idx0 = (long long)row * N + col;
            long long idx1 = (long long)(row + 8) * N + col;
            *(__half2*)(Ch + idx0) = __halves2half2(__float2half_rn(v0.x), __float2half_rn(v0.y));
            *(__half2*)(Ch + idx1) = __halves2half2(__float2half_rn(v1.x), __float2half_rn(v1.y));
        }
}

// ----------------------------------------------------------------------------
// Fused: entropy + fp16 convert of feats + total (slot 3)
// ----------------------------------------------------------------------------
__global__ void prep_feats(const float* __restrict__ text,
                           const float* __restrict__ audio,
                           const float* __restrict__ visual) {
    __shared__ float sh[3][4];
    long long r = blockIdx.x;
    int tid = threadIdx.x, lane = tid & 31, w = tid >> 5;
    long long off = r * HH + tid * 4;
    float4 v0 = *(const float4*)(text + off);
    float4 v1 = *(const float4*)(audio + off);
    float4 v2 = *(const float4*)(visual + off);

    float a0x = fabsf(v0.x), a0y = fabsf(v0.y), a0z = fabsf(v0.z), a0w = fabsf(v0.w);
    float a1x = fabsf(v1.x), a1y = fabsf(v1.y), a1z = fabsf(v1.z), a1w = fabsf(v1.w);
    float a2x = fabsf(v2.x), a2y = fabsf(v2.y), a2z = fabsf(v2.z), a2w = fabsf(v2.w);
    float s0 = a0x + a0y + a0z + a0w;
    float s1 = a1x + a1y + a1z + a1w;
    float s2 = a2x + a2y + a2z + a2w;
    #pragma unroll
    for (int o = 16; o; o >>= 1) {
        s0 += __shfl_down_sync(0xffffffffu, s0, o);
        s1 += __shfl_down_sync(0xffffffffu, s1, o);
        s2 += __shfl_down_sync(0xffffffffu, s2, o);
    }
    if (lane == 0) { sh[0][w] = s0; sh[1][w] = s1; sh[2][w] = s2; }
    __syncthreads();
    float t0 = sh[0][0] + sh[0][1] + sh[0][2] + sh[0][3];
    float t1 = sh[1][0] + sh[1][1] + sh[1][2] + sh[1][3];
    float t2 = sh[2][0] + sh[2][1] + sh[2][2] + sh[2][3];
    float i0 = 1.0f / (t0 + EPSV), i1 = 1.0f / (t1 + EPSV), i2 = 1.0f / (t2 + EPSV);

    float e0, e1, e2;
    {
        float f0 = a0x * i0, f1 = a0y * i0, f2 = a0z * i0, f3 = a0w * i0;
        e0 = f0 * logf(f0 + EPSV) + f1 * logf(f1 + EPSV)
           + f2 * logf(f2 + EPSV) + f3 * logf(f3 + EPSV);
    }
    {
        float f0 = a1x * i1, f1 = a1y * i1, f2 = a1z * i1, f3 = a1w * i1;
        e1 = f0 * logf(f0 + EPSV) + f1 * logf(f1 + EPSV)
           + f2 * logf(f2 + EPSV) + f3 * logf(f3 + EPSV);
    }
    {
        float f0 = a2x * i2, f1 = a2y * i2, f2 = a2z * i2, f3 = a2w * i2;
        e2 = f0 * logf(f0 + EPSV) + f1 * logf(f1 + EPSV)
           + f2 * logf(f2 + EPSV) + f3 * logf(f3 + EPSV);
    }
    #pragma unroll
    for (int o = 16; o; o >>= 1) {
        e0 += __shfl_down_sync(0xffffffffu, e0, o);
        e1 += __shfl_down_sync(0xffffffffu, e1, o);
        e2 += __shfl_down_sync(0xffffffffu, e2, o);
    }
    __syncthreads();
    if (lane == 0) { sh[0][w] = e0; sh[1][w] = e1; sh[2][w] = e2; }
    __syncthreads();
    if (tid == 0) {
        g_ent[0 * MM + r] = -(sh[0][0] + sh[0][1] + sh[0][2] + sh[0][3]);
        g_ent[1 * MM + r] = -(sh[1][0] + sh[1][1] + sh[1][2] + sh[1][3]);
        g_ent[2 * MM + r] = -(sh[2][0] + sh[2][1] + sh[2][2] + sh[2][3]);
    }

    store4h(v0, g_f, 0LL * MM * HH + off);
    store4h(v1, g_f, 1LL * MM * HH + off);
    store4h(v2, g_f, 2LL * MM * HH + off);
    float4 tq = make_float4(v0.x + v1.x + v2.x, v0.y + v1.y + v2.y,
                            v0.z + v1.z + v2.z, v0.w + v1.w + v2.w);
    store4h(tq, g_f, 3LL * MM * HH + off);
}

// ----------------------------------------------------------------------------
// Weight prep (merged: gate weights + Wc transpose)
// ----------------------------------------------------------------------------
__global__ void prep_weights(const float* __restrict__ gW, const float* __restrict__ Wc) {
    int idx = blockIdx.x * blockDim.x + threadIdx.x;
    if (idx < HH * HH) {
        float wa = gW[idx];
        float wb = gW[HH * HH + idx];
        float wc = gW[2 * HH * HH + idx];
        g_Aw[idx] = __float2half_rn(wa + wb - 0.5f * wc);
        g_Wh[idx] = __float2half_rn(0.5f * wc);
    }
    if (idx < HH) g_wlast[idx] = gW[3 * HH * HH + idx];
    if (idx < HH * CC) {
        int k = idx / CC, c = idx % CC;
        g_WcT[c * HH + k] = Wc[k * CC + c];
    }
}

__global__ void conv_w(const float* __restrict__ src, __half* __restrict__ dst, int n4) {
    int i = blockIdx.x * blockDim.x + threadIdx.x;
    if (i < n4) {
        float4 v = ((const float4*)src)[i];
        store4h(v, dst, (long long)i * 4);
    }
}

// ----------------------------------------------------------------------------
// gate_fuse: h0 = sigmoid(G + T + ent*wlast + gate_b) * feat  (fp16 feat read)
// ----------------------------------------------------------------------------
__global__ void gate_fuse_kernel(const float* __restrict__ gate_b) {
    long long r = blockIdx.x;
    int m = blockIdx.y;
    float e = g_ent[(long long)m * MM + r];
    int j = threadIdx.x * 4;
    long long gi = ((long long)m * MM + r) * HH + j;
    long long ti = (3LL * MM + r) * HH + j;
    float2 gv0 = __half22float2(*(const __half2*)(g_G + gi));
    float2 gv1 = __half22float2(*(const __half2*)(g_G + gi + 2));
    float2 tv0 = __half22float2(*(const __half2*)(g_G + ti));
    float2 tv1 = __half22float2(*(const __half2*)(g_G + ti + 2));
    float2 fv0 = __half22float2(*(const __half2*)(g_f + gi));
    float2 fv1 = __half22float2(*(const __half2*)(g_f + gi + 2));
    float4 wv = *(const float4*)(g_wlast + j);
    float4 bv = *(const float4*)(gate_b + j);

    float zx = gv0.x + tv0.x + e * wv.x + bv.x;
    float zy = gv0.y + tv0.y + e * wv.y + bv.y;
    float zz = gv1.x + tv1.x + e * wv.z + bv.z;
    float zw = gv1.y + tv1.y + e * wv.w + bv.w;
    float4 o;
    o.x = fv0.x / (1.0f + expf(-zx));
    o.y = fv0.y / (1.0f + expf(-zy));
    o.z = fv1.x / (1.0f + expf(-zz));
    o.w = fv1.y / (1.0f + expf(-zw));
    store4h(o, g_h0, r * H3 + m * HH + j);
}

// ----------------------------------------------------------------------------
// Degree: dsi + cache fp16(sp+tp)
// ----------------------------------------------------------------------------
__global__ void degree_kernel(const float* __restrict__ sp, const float* __restrict__ tp) {
    __shared__ float sh[8];
    long long b = blockIdx.y, i = blockIdx.x;
    long long base = (b * SS + i) * SS;
    const float4* rs = (const float4*)(sp + base);
    const float4* rt = (const float4*)(tp + base);
    float4 a = rs[threadIdx.x], c = rt[threadIdx.x];
    float4 sm4 = make_float4(a.x + c.x, a.y + c.y, a.z + c.z, a.w + c.w);
    store4h(sm4, g_sumh, base + threadIdx.x * 4);
    float s = sm4.x + sm4.y + sm4.z + sm4.w;
    #pragma unroll
    for (int o = 16; o; o >>= 1) s += __shfl_down_sync(0xffffffffu, s, o);
    int lane = threadIdx.x & 31, w = threadIdx.x >> 5;
    if (lane == 0) sh[w] = s;
    __syncthreads();
    if (threadIdx.x == 0) {
        float D = 1.0f + 0.5f * (sh[0] + sh[1] + sh[2] + sh[3] + sh[4] + sh[5] + sh[6] + sh[7]);
        g_dsi[b * SS + i] = 1.0f / sqrtf(D + EPSV);
    }
}

__global__ void normadj_kernel() {
    long long n4 = (long long)BB * SS * SS / 4;
    for (long long g = (long long)blockIdx.x * blockDim.x + threadIdx.x; g < n4;
         g += (long long)gridDim.x * blockDim.x) {
        long long e = g * 4;
        int b = (int)(e / ((long long)SS * SS));
        long long rrem = e % ((long long)SS * SS);
        int i = (int)(rrem / SS);
        int j = (int)(rrem % SS);
        float2 s0 = __half22float2(*(const __half2*)(g_sumh + e));
        float2 s1 = __half22float2(*(const __half2*)(g_sumh + e + 2));
        float di = g_dsi[(long long)b * SS + i];
        const float* dj = g_dsi + (long long)b * SS + j;
        float4 o;
        o.x = (0.5f * s0.x + (j + 0 == i ? 1.0f : 0.0f)) * di * dj[0];
        o.y = (0.5f * s0.y + (j + 1 == i ? 1.0f : 0.0f)) * di * dj[1];
        o.z = (0.5f * s1.x + (j + 2 == i ? 1.0f : 0.0f)) * di * dj[2];
        o.w = (0.5f * s1.y + (j + 3 == i ? 1.0f : 0.0f)) * di * dj[3];
        store4h(o, g_adj, e);
    }
}

// ----------------------------------------------------------------------------
// Classifier
// ----------------------------------------------------------------------------
__global__ void classifier_kernel(const float* __restrict__ bc, float* __restrict__ out) {
    __shared__ float sh[HH];
    long long r = blockIdx.x;
    for (int k = threadIdx.x; k < HH; k += 224)
        sh[k] = __half2float(g_h[r * HH + k]);
    __syncthreads();
    int w = threadIdx.x >> 5, lane = threadIdx.x & 31;
    if (w < CC) {
        const float* wrow = g_WcT + w * HH;
        float s = 0.0f;
        #pragma unroll
        for (int k = lane; k < HH; k += 32) s += sh[k] * wrow[k];
        #pragma unroll
        for (int o = 16; o; o >>= 1) s += __shfl_down_sync(0xffffffffu, s, o);
        if (lane == 0) out[r * CC + w] = s + bc[w];
    }
}

// ----------------------------------------------------------------------------
// Launch — adjacency/weight prep forked onto a side stream, overlapping the
// gating GEMM phase; event join before the GNN GEMMs.
// ----------------------------------------------------------------------------
extern "C" void kernel_launch(void* const* d_in, const int* in_sizes, int n_in,
                              void* d_out, int out_size) {
    const float* text   = (const float*)d_in[0];
    const float* audio  = (const float*)d_in[1];
    const float* visual = (const float*)d_in[2];
    const float* sp     = (const float*)d_in[3];
    const float* tp     = (const float*)d_in[4];
    const float* gate_W = (const float*)d_in[6];
    const float* gate_b = (const float*)d_in[7];
    const float* W0 = (const float*)d_in[8];
    const float* b0 = (const float*)d_in[9];
    const float* W1 = (const float*)d_in[10];
    const float* b1 = (const float*)d_in[11];
    const float* W2 = (const float*)d_in[12];
    const float* b2 = (const float*)d_in[13];
    const float* Wc = (const float*)d_in[14];
    const float* bc = (const float*)d_in[15];
    float* out = (float*)d_out;

    static bool init_done = false;
    static cudaStream_t s2;
    static cudaEvent_t eFork, eJoin;
    if (!init_done) {
        cudaFuncSetAttribute(mma_gemm<0, 0>, cudaFuncAttributeMaxDynamicSharedMemorySize, SMEM_BYTES);
        cudaFuncSetAttribute(mma_gemm<1, 0>, cudaFuncAttributeMaxDynamicSharedMemorySize, SMEM_BYTES);
        cudaFuncSetAttribute(mma_gemm<0, 1>, cudaFuncAttributeMaxDynamicSharedMemorySize, SMEM_BYTES);
        cudaStreamCreateWithFlags(&s2, cudaStreamNonBlocking);
        cudaEventCreateWithFlags(&eFork, cudaEventDisableTiming);
        cudaEventCreateWithFlags(&eJoin, cudaEventDisableTiming);
        init_done = true;
    }

    #define SYM(p, s) cudaGetSymbolAddress((void**)&p, s)
    __half *f, *G, *h0, *adj, *tmp, *h;
    __half *Aw, *Wh, *W0p, *W1p, *W2p;
    SYM(f, g_f); SYM(G, g_G);
    SYM(h0, g_h0); SYM(adj, g_adj);
    SYM(tmp, g_tmp); SYM(h, g_h);
    SYM(Aw, g_Aw); SYM(Wh, g_Wh);
    SYM(W0p, g_W0); SYM(W1p, g_W1); SYM(W2p, g_W2);
    #undef SYM

    long long sF = (long long)MM * HH;
    dim3 gemm_grid(HH / BN, MM / BM, 1);
    dim3 gate_grid(HH / BN, MM / BM, 4);
    dim3 adj_grid(HH / BN, SS / BM, BB);
    long long sAdj = (long long)SS * SS, sL = (long long)SS * HH;

    // fork: adjacency + GNN weight prep on side stream (independent of gating)
    cudaEventRecord(eFork, 0);
    cudaStreamWaitEvent(s2, eFork, 0);
    degree_kernel<<<dim3(SS, BB), 256, 0, s2>>>(sp, tp);
    normadj_kernel<<<8192, 256, 0, s2>>>();
    conv_w<<<(H3 * HH / 4 + 255) / 256, 256, 0, s2>>>(W0, W0p, H3 * HH / 4);
    conv_w<<<(HH * HH / 4 + 255) / 256, 256, 0, s2>>>(W1, W1p, HH * HH / 4);
    conv_w<<<(HH * HH / 4 + 255) / 256, 256, 0, s2>>>(W2, W2p, HH * HH / 4);
    cudaEventRecord(eJoin, s2);

    // main stream: gating path
    prep_weights<<<(HH * HH + 255) / 256, 256>>>(gate_W, Wc);
    prep_feats<<<MM, 128>>>(text, audio, visual);
    mma_gemm<0, 1><<<gate_grid, 256, SMEM_BYTES>>>(f, Aw, Wh, nullptr, G,
                                                   MM, HH, HH, sF, 0, sF);
    gate_fuse_kernel<<<dim3(MM, 3), 128>>>(gate_b);

    // join before GNN
    cudaStreamWaitEvent(0, eJoin, 0);

    // spectral GNN (all GEMMs 1 MMA)
    mma_gemm<0, 0><<<gemm_grid, 256, SMEM_BYTES>>>(h0, W0p, nullptr, nullptr, tmp,
                                                   MM, HH, H3, 0, 0, 0);
    mma_gemm<1, 0><<<adj_grid, 256, SMEM_BYTES>>>(adj, tmp, nullptr, b0, h,
                                                  SS, HH, SS, sAdj, sL, sL);

    mma_gemm<0, 0><<<gemm_grid, 256, SMEM_BYTES>>>(h, W1p, nullptr, nullptr, tmp,
                                                   MM, HH, HH, 0, 0, 0);
    mma_gemm<1, 0><<<adj_grid, 256, SMEM_BYTES>>>(adj, tmp, nullptr, b1, h,
                                                  SS, HH, SS, sAdj, sL, sL);

    mma_gemm<0, 0><<<gemm_grid, 256, SMEM_BYTES>>>(h, W2p, nullptr, nullptr, tmp,
                                                   MM, HH, HH, 0, 0, 0);
    mma_gemm<1, 0><<<adj_grid, 256, SMEM_BYTES>>>(adj, tmp, nullptr, b2, h,
                                                  SS, HH, SS, sAdj, sL, sL);

    // classifier
    classifier_kernel<<<MM, 224>>>(bc, out);
}